// round 2
// baseline (speedup 1.0000x reference)
#include <cuda_runtime.h>
#include <math.h>

#define BEPS 1e-5f

// ---------------- scratch (static device globals; no allocation) ----------------
__device__ float g_h1[4*64*2048];          // conv1 output (post BN+relu)
__device__ float g_h2[4*128*2048];         // conv2 pre-act, then post BN+relu in place
__device__ float g_sc1[64], g_sh1[64];
__device__ float g_c2sum[128], g_c2ss[128];
__device__ float g_sc2[128], g_sh2[128];
__device__ float g_rowstats[16384*10];     // per (q,p): sum, sumsq, max[4], min[4]
__device__ float g_u[4*1024*16];           // squashed primary caps [b][p][q]
__device__ float g_uhat[(long)4*64*1024*64]; // 67MB  [b][l][p][v]
__device__ float g_bij[4*64*1024];
__device__ float g_cij[4*64*1024];
__device__ float g_vj[4*64*64];

// ---------------- zero the accumulators that need it each launch ----------------
__global__ void k_zero() {
    int i = blockIdx.x*256 + threadIdx.x;
    if (i < 4*64*1024) g_bij[i] = 0.f;
    if (i < 128) { g_c2sum[i] = 0.f; g_c2ss[i] = 0.f; }
}

// ---------------- BN1 params from analytic stats of x (linear layer) ------------
__global__ void k_bn1(const float* __restrict__ x, const float* __restrict__ w1,
                      const float* __restrict__ b1, const float* __restrict__ g1,
                      const float* __restrict__ be1) {
    float s0=0,s1=0,s2=0,p00=0,p01=0,p02=0,p11=0,p12=0,p22=0;
    for (int i = threadIdx.x; i < 8192; i += 256) {
        int b = i >> 11, n = i & 2047;
        const float* xb = x + b*3*2048 + n;
        float a = xb[0], c = xb[2048], d = xb[4096];
        s0+=a; s1+=c; s2+=d;
        p00+=a*a; p01+=a*c; p02+=a*d; p11+=c*c; p12+=c*d; p22+=d*d;
    }
    __shared__ float red[9][8];
    __shared__ float m[3], cov[3][3];
    float vals[9] = {s0,s1,s2,p00,p01,p02,p11,p12,p22};
    int lane = threadIdx.x & 31, w = threadIdx.x >> 5;
    #pragma unroll
    for (int j=0;j<9;j++) {
        float v = vals[j];
        #pragma unroll
        for (int o=16;o>0;o>>=1) v += __shfl_down_sync(0xffffffffu, v, o);
        if (lane==0) red[j][w] = v;
    }
    __syncthreads();
    if (threadIdx.x < 9) {
        float v = 0;
        for (int ww=0; ww<8; ww++) v += red[threadIdx.x][ww];
        red[threadIdx.x][0] = v * (1.f/8192.f);
    }
    __syncthreads();
    if (threadIdx.x == 0) {
        m[0]=red[0][0]; m[1]=red[1][0]; m[2]=red[2][0];
        cov[0][0]=red[3][0]-m[0]*m[0];
        cov[0][1]=cov[1][0]=red[4][0]-m[0]*m[1];
        cov[0][2]=cov[2][0]=red[5][0]-m[0]*m[2];
        cov[1][1]=red[6][0]-m[1]*m[1];
        cov[1][2]=cov[2][1]=red[7][0]-m[1]*m[2];
        cov[2][2]=red[8][0]-m[2]*m[2];
    }
    __syncthreads();
    if (threadIdx.x < 64) {
        int o = threadIdx.x;
        float wv0=w1[o*3], wv1=w1[o*3+1], wv2=w1[o*3+2];
        float mean = wv0*m[0]+wv1*m[1]+wv2*m[2] + b1[o];
        float var = wv0*wv0*cov[0][0] + wv1*wv1*cov[1][1] + wv2*wv2*cov[2][2]
                  + 2.f*(wv0*wv1*cov[0][1] + wv0*wv2*cov[0][2] + wv1*wv2*cov[1][2]);
        float sc = g1[o]*rsqrtf(var + BEPS);
        g_sc1[o] = sc;
        g_sh1[o] = be1[o] - mean*sc;
    }
}

// ---------------- conv1 + BN + relu ----------------
__global__ void k_conv1(const float* __restrict__ x, const float* __restrict__ w1,
                        const float* __restrict__ b1) {
    int n = blockIdx.x*256 + threadIdx.x;
    int b = blockIdx.y;
    float x0 = x[b*6144 + n], x1 = x[b*6144 + 2048 + n], x2 = x[b*6144 + 4096 + n];
    #pragma unroll 8
    for (int o=0;o<64;o++) {
        float pre = fmaf(w1[o*3], x0, fmaf(w1[o*3+1], x1, fmaf(w1[o*3+2], x2, b1[o])));
        float h = fmaf(g_sc1[o], pre, g_sh1[o]);
        g_h1[(b*64+o)*2048 + n] = fmaxf(h, 0.f);
    }
}

// ---------------- conv2 pre-act + per-channel stats ----------------
__global__ void k_conv2(const float* __restrict__ w2, const float* __restrict__ b2) {
    int b = blockIdx.y, n0 = blockIdx.x*128, t = threadIdx.x;
    __shared__ float hs[64][128];
    __shared__ float ssum[128], sss[128];
    for (int c=0;c<64;c++) hs[c][t] = g_h1[(b*64+c)*2048 + n0 + t];
    ssum[t] = 0.f; sss[t] = 0.f;
    __syncthreads();
    int lane = t & 31;
    for (int o=0;o<128;o++) {
        float acc = b2[o];
        #pragma unroll
        for (int c=0;c<64;c++) acc = fmaf(w2[o*64+c], hs[c][t], acc);
        g_h2[(b*128+o)*2048 + n0 + t] = acc;
        float s = acc, q = acc*acc;
        #pragma unroll
        for (int off=16;off>0;off>>=1) {
            s += __shfl_down_sync(0xffffffffu, s, off);
            q += __shfl_down_sync(0xffffffffu, q, off);
        }
        if (lane==0) { atomicAdd(&ssum[o], s); atomicAdd(&sss[o], q); }
    }
    __syncthreads();
    atomicAdd(&g_c2sum[t], ssum[t]);
    atomicAdd(&g_c2ss[t], sss[t]);
}

__global__ void k_bn2fin(const float* __restrict__ g2, const float* __restrict__ be2) {
    int c = threadIdx.x;
    float mean = g_c2sum[c] * (1.f/8192.f);
    float var = g_c2ss[c] * (1.f/8192.f) - mean*mean;
    float sc = g2[c]*rsqrtf(var + BEPS);
    g_sc2[c] = sc;
    g_sh2[c] = be2[c] - mean*sc;
}

__global__ void k_relu2() {
    int i = blockIdx.x*256 + threadIdx.x;
    int c = (i >> 11) & 127;
    float v = g_h2[i];
    g_h2[i] = fmaxf(fmaf(g_sc2[c], v, g_sh2[c]), 0.f);
}

// ---------------- primary caps: 16384x8192x128 GEMM fused with row stats -------
// Tile: 128 rows x 256 cols, 256 threads, each thread 16 rows x 8 cols.
#define KC 16
__global__ void __launch_bounds__(256,1)
k_caps(const float* __restrict__ w3, const float* __restrict__ b3) {
    __shared__ float As[KC][128];
    __shared__ float Bs[KC][256];
    __shared__ float s_sum[128], s_ss[128], s_mx[4][128], s_mn[4][128];
    int t  = threadIdx.x;
    int tx = t & 31;    // col group -> cols tx*8..+7
    int ty = t >> 5;    // row group -> rows ty*16..+15  (whole warp shares ty)
    int row0 = blockIdx.x * 128;

    for (int i=t;i<128;i+=256){ s_sum[i]=0.f; s_ss[i]=0.f; }
    for (int i=t;i<512;i+=256){ ((float*)s_mx)[i]=-3.4e38f; ((float*)s_mn)[i]=3.4e38f; }
    float bias[16];
    #pragma unroll
    for (int r=0;r<16;r++) bias[r] = b3[row0 + ty*16 + r];
    __syncthreads();

    for (int ct = 0; ct < 32; ct++) {
        int cb = ct >> 3;            // batch of this column tile
        int n0 = (ct & 7) * 256;
        float acc[16][8];
        #pragma unroll
        for (int r=0;r<16;r++)
            #pragma unroll
            for (int c=0;c<8;c++) acc[r][c]=0.f;

        for (int kc = 0; kc < 128; kc += KC) {
            {   // A tile (transposed to As[k][row])
                int r = t >> 1, ko = (t & 1)*8;
                const float* src = w3 + (row0 + r)*128 + kc + ko;
                float4 v0 = *(const float4*)src;
                float4 v1 = *(const float4*)(src+4);
                As[ko+0][r]=v0.x; As[ko+1][r]=v0.y; As[ko+2][r]=v0.z; As[ko+3][r]=v0.w;
                As[ko+4][r]=v1.x; As[ko+5][r]=v1.y; As[ko+6][r]=v1.z; As[ko+7][r]=v1.w;
            }
            #pragma unroll
            for (int i=0;i<4;i++) {   // B tile
                int f = t + i*256;
                int k = f >> 6;
                int c = (f & 63)*4;
                *(float4*)&Bs[k][c] =
                    *(const float4*)&g_h2[((cb*128)+(kc+k))*2048 + n0 + c];
            }
            __syncthreads();
            #pragma unroll 4
            for (int k=0;k<KC;k++) {
                float a[16], bb[8];
                #pragma unroll
                for (int i=0;i<4;i++) *(float4*)&a[i*4] = *(const float4*)&As[k][ty*16 + i*4];
                *(float4*)&bb[0] = *(const float4*)&Bs[k][tx*8];
                *(float4*)&bb[4] = *(const float4*)&Bs[k][tx*8+4];
                #pragma unroll
                for (int r=0;r<16;r++)
                    #pragma unroll
                    for (int c=0;c<8;c++) acc[r][c] = fmaf(a[r], bb[c], acc[r][c]);
            }
            __syncthreads();
        }
        // fold this column tile into the row statistics
        #pragma unroll
        for (int r=0;r<16;r++) {
            float s=0.f, q=0.f, mx=-3.4e38f, mn=3.4e38f;
            #pragma unroll
            for (int c=0;c<8;c++) {
                float v = acc[r][c] + bias[r];
                s += v; q = fmaf(v,v,q); mx = fmaxf(mx,v); mn = fminf(mn,v);
            }
            #pragma unroll
            for (int off=16;off>0;off>>=1) {
                s  += __shfl_down_sync(0xffffffffu, s, off);
                q  += __shfl_down_sync(0xffffffffu, q, off);
                mx = fmaxf(mx, __shfl_down_sync(0xffffffffu, mx, off));
                mn = fminf(mn, __shfl_down_sync(0xffffffffu, mn, off));
            }
            if (tx == 0) {   // each warp owns rows ty*16..+15 exclusively
                int rr = ty*16 + r;
                s_sum[rr] += s; s_ss[rr] += q;
                s_mx[cb][rr] = fmaxf(s_mx[cb][rr], mx);
                s_mn[cb][rr] = fminf(s_mn[cb][rr], mn);
            }
        }
    }
    __syncthreads();
    if (t < 128) {
        int row = row0 + t;
        float* o = g_rowstats + row*10;
        o[0] = s_sum[t]; o[1] = s_ss[t];
        #pragma unroll
        for (int b=0;b<4;b++){ o[2+b]=s_mx[b][t]; o[6+b]=s_mn[b][t]; }
    }
}

// ---------------- finalize BN + max + squash -> u[b][p][q] ----------------
__global__ void k_ufin(const float* __restrict__ g3, const float* __restrict__ be3) {
    int idx = blockIdx.x*256 + threadIdx.x;   // 4096 (b,p)
    int b = idx >> 10, p = idx & 1023;
    float vq[16]; float sn = 0.f;
    #pragma unroll
    for (int q=0;q<16;q++) {
        int row = q*1024 + p;
        const float* st = g_rowstats + row*10;
        float mean = st[0]*(1.f/8192.f);
        float var  = st[1]*(1.f/8192.f) - mean*mean;
        float sc = g3[row]*rsqrtf(var + BEPS);
        float m = (sc >= 0.f) ? st[2+b] : st[6+b];   // BN affine is monotone
        float v = fmaf(sc, m - mean, be3[row]);
        vq[q] = v; sn = fmaf(v,v,sn);
    }
    float coef = sn/((1.f+sn)*sqrtf(sn));
    #pragma unroll
    for (int q=0;q<16;q++) g_u[(b*1024+p)*16 + q] = coef*vq[q];
}

// ---------------- u_hat = einsum(lpvq,bpq->blpv) ----------------
__global__ void k_uhat(const float* __restrict__ Wr) {
    int bid = blockIdx.x;                 // 16384: l, group of 4 p
    int l = bid >> 8, p0 = (bid & 255)*4;
    int t = threadIdx.x, pi = t >> 6, v = t & 63;
    int p = p0 + pi;
    __shared__ float us[4][4][16];        // [pi][b][q]
    { int pp = t>>6, bb=(t>>4)&3, q=t&15;
      us[pp][bb][q] = g_u[(bb*1024 + p0+pp)*16 + q]; }
    __syncthreads();
    const float* wr = Wr + (((long)(l*1024+p))*64 + v)*16;
    float4 a0 = *(const float4*)wr,     a1 = *(const float4*)(wr+4);
    float4 a2 = *(const float4*)(wr+8), a3 = *(const float4*)(wr+12);
    #pragma unroll
    for (int b=0;b<4;b++) {
        const float* u = us[pi][b];
        float d = a0.x*u[0]+a0.y*u[1]+a0.z*u[2]+a0.w*u[3]
                + a1.x*u[4]+a1.y*u[5]+a1.z*u[6]+a1.w*u[7]
                + a2.x*u[8]+a2.y*u[9]+a2.z*u[10]+a2.w*u[11]
                + a3.x*u[12]+a3.y*u[13]+a3.z*u[14]+a3.w*u[15];
        g_uhat[(((long)(b*64+l))*1024+p)*64 + v] = d;
    }
}

// ---------------- routing: softmax over L ----------------
__global__ void k_softmax() {
    int idx = blockIdx.x*256 + threadIdx.x;  // 4096 (b,p)
    int b = idx >> 10, p = idx & 1023;
    const float* bp = g_bij + b*65536 + p;
    float e[64]; float mx = -3.4e38f;
    #pragma unroll
    for (int l=0;l<64;l++){ e[l] = bp[l*1024]; mx = fmaxf(mx, e[l]); }
    float s = 0.f;
    #pragma unroll
    for (int l=0;l<64;l++){ e[l] = __expf(e[l]-mx); s += e[l]; }
    float inv = 1.f/s;
    float* cp = g_cij + b*65536 + p;
    #pragma unroll
    for (int l=0;l<64;l++) cp[l*1024] = e[l]*inv;
}

// ---------------- routing: v_j = squash(sum_p c*u_hat) ----------------
__global__ void k_vj() {
    int bid = blockIdx.x;                 // 256 (b,l)
    int b = bid >> 6, l = bid & 63;
    int t = threadIdx.x, v = t & 63, pc = t >> 6;
    __shared__ float cs[1024];
    __shared__ float red[4][64];
    __shared__ float sq[64];
    __shared__ float s_coef;
    for (int i=t;i<1024;i+=256) cs[i] = g_cij[(b*64+l)*1024 + i];
    __syncthreads();
    const float* uh = g_uhat + ((long)(b*64+l))*65536;
    float acc = 0.f;
    #pragma unroll 8
    for (int p = pc*256; p < pc*256+256; p++)
        acc = fmaf(cs[p], uh[p*64 + v], acc);
    red[pc][v] = acc;
    __syncthreads();
    if (t < 64) {
        float vr = red[0][t]+red[1][t]+red[2][t]+red[3][t];
        red[0][t] = vr;
        sq[t] = vr*vr;
    }
    __syncthreads();
    if (t == 0) {
        float sn = 0.f;
        for (int i=0;i<64;i++) sn += sq[i];
        s_coef = sn/((1.f+sn)*sqrtf(sn));
    }
    __syncthreads();
    if (t < 64) g_vj[(b*64+l)*64 + t] = s_coef*red[0][t];
}

// ---------------- routing: b_ij += <v_j, u_hat> ----------------
__global__ void k_bupd() {
    int bid = blockIdx.x;
    int b = bid >> 6, l = bid & 63;
    int t = threadIdx.x, lane = t & 31, w = t >> 5;
    __shared__ float vs[64];
    if (t < 64) vs[t] = g_vj[(b*64+l)*64 + t];
    __syncthreads();
    float v0 = vs[lane], v1 = vs[lane+32];
    const float* uh = g_uhat + ((long)(b*64+l))*65536;
    float* bp = g_bij + (b*64+l)*1024;
    for (int p = w; p < 1024; p += 8) {
        float d = fmaf(v0, uh[p*64+lane], v1*uh[p*64+lane+32]);
        #pragma unroll
        for (int off=16;off>0;off>>=1) d += __shfl_down_sync(0xffffffffu, d, off);
        if (lane==0) bp[p] += d;
    }
}

// ---------------- head: logits + presence ----------------
__global__ void k_logits(const float* __restrict__ fcw, const float* __restrict__ fcb,
                         float* __restrict__ out) {
    int bid = blockIdx.x;                 // 160 = 4*40
    int b = bid/40, o = bid%40;
    int t = threadIdx.x;                  // 128
    const float* vj = g_vj + b*4096;
    const float* wr = fcw + o*4096;
    float acc = 0.f;
    for (int i=t;i<4096;i+=128) acc = fmaf(vj[i], wr[i], acc);
    __shared__ float red[4];
    #pragma unroll
    for (int off=16;off>0;off>>=1) acc += __shfl_down_sync(0xffffffffu, acc, off);
    if ((t&31)==0) red[t>>5]=acc;
    __syncthreads();
    if (t==0) out[b*40+o] = red[0]+red[1]+red[2]+red[3] + fcb[o];
}

__global__ void k_pres(float* __restrict__ out) {
    int t = threadIdx.x;                  // 256 = (b,l)
    const float* vj = g_vj + t*64;
    float s = 0.f;
    #pragma unroll
    for (int i=0;i<64;i++) s = fmaf(vj[i], vj[i], s);
    out[160 + t] = sqrtf(s);
}

// ---------------- launch ----------------
extern "C" void kernel_launch(void* const* d_in, const int* in_sizes, int n_in,
                              void* d_out, int out_size) {
    const float* x   = (const float*)d_in[0];
    const float* w1  = (const float*)d_in[1];
    const float* b1  = (const float*)d_in[2];
    const float* g1  = (const float*)d_in[3];
    const float* be1 = (const float*)d_in[4];
    const float* w2  = (const float*)d_in[5];
    const float* b2  = (const float*)d_in[6];
    const float* g2  = (const float*)d_in[7];
    const float* be2 = (const float*)d_in[8];
    const float* w3  = (const float*)d_in[9];
    const float* b3  = (const float*)d_in[10];
    const float* g3  = (const float*)d_in[11];
    const float* be3 = (const float*)d_in[12];
    const float* Wr  = (const float*)d_in[13];
    const float* fcw = (const float*)d_in[14];
    const float* fcb = (const float*)d_in[15];
    float* out = (float*)d_out;

    k_zero<<<1024,256>>>();
    k_bn1<<<1,256>>>(x,w1,b1,g1,be1);
    k_conv1<<<dim3(8,4),256>>>(x,w1,b1);
    k_conv2<<<dim3(16,4),128>>>(w2,b2);
    k_bn2fin<<<1,128>>>(g2,be2);
    k_relu2<<<4096,256>>>();
    k_caps<<<128,256>>>(w3,b3);
    k_ufin<<<16,256>>>(g3,be3);
    k_uhat<<<16384,256>>>(Wr);
    for (int it=0; it<3; it++) {
        k_softmax<<<16,256>>>();
        k_vj<<<256,256>>>();
        if (it<2) k_bupd<<<256,256>>>();
    }
    k_logits<<<160,128>>>(fcw, fcb, out);
    k_pres<<<1,256>>>(out);
}

// round 4
// speedup vs baseline: 2.6642x; 2.6642x over previous
#include <cuda_runtime.h>
#include <cuda_bf16.h>
#include <mma.h>
#include <cstdint>
#include <math.h>

using namespace nvcuda;

#define BEPS 1e-5f

// ---------------- scratch (static device globals; no allocation) ----------------
__device__ float g_h1[4*64*2048];            // conv1 output (post BN+relu)
__device__ float g_h2[4*128*2048];           // conv2 pre-act
__device__ float g_sc1[64], g_sh1[64];
__device__ float g_c2sum[128], g_c2ss[128];
__device__ float g_sc2[128], g_sh2[128];
__device__ __align__(16) __nv_bfloat16 g_As[16384*384];  // A' = [hi|hi|lo]
__device__ __align__(16) __nv_bfloat16 g_Bs[8192*384];   // B' = [hi|lo|hi]
__device__ float g_psum[16384*64], g_pss[16384*64], g_pmx[16384*64], g_pmn[16384*64];
__device__ float g_rowstats[16384*10];       // per (q,p): sum, sumsq, max[4], min[4]
__device__ float g_u[4*1024*16];             // squashed primary caps [b][p][q]
__device__ float g_uhat[(long)4*64*1024*64]; // 67MB [b][l][p][v]
__device__ float g_bij[4*64*1024];
__device__ float g_cij[4*64*1024];
__device__ float g_vj[4*64*64];

// ---------------- zero the accumulators that need it each launch ----------------
__global__ void k_zero() {
    int i = blockIdx.x*256 + threadIdx.x;
    if (i < 4*64*1024) g_bij[i] = 0.f;
    if (i < 128) { g_c2sum[i] = 0.f; g_c2ss[i] = 0.f; }
}

// ---------------- BN1 params from analytic stats of x (linear layer) ------------
__global__ void k_bn1(const float* __restrict__ x, const float* __restrict__ w1,
                      const float* __restrict__ b1, const float* __restrict__ g1,
                      const float* __restrict__ be1) {
    float s0=0,s1=0,s2=0,p00=0,p01=0,p02=0,p11=0,p12=0,p22=0;
    for (int i = threadIdx.x; i < 8192; i += 256) {
        int b = i >> 11, n = i & 2047;
        const float* xb = x + b*3*2048 + n;
        float a = xb[0], c = xb[2048], d = xb[4096];
        s0+=a; s1+=c; s2+=d;
        p00+=a*a; p01+=a*c; p02+=a*d; p11+=c*c; p12+=c*d; p22+=d*d;
    }
    __shared__ float red[9][8];
    __shared__ float m[3], cov[3][3];
    float vals[9] = {s0,s1,s2,p00,p01,p02,p11,p12,p22};
    int lane = threadIdx.x & 31, w = threadIdx.x >> 5;
    #pragma unroll
    for (int j=0;j<9;j++) {
        float v = vals[j];
        #pragma unroll
        for (int o=16;o>0;o>>=1) v += __shfl_down_sync(0xffffffffu, v, o);
        if (lane==0) red[j][w] = v;
    }
    __syncthreads();
    if (threadIdx.x < 9) {
        float v = 0;
        for (int ww=0; ww<8; ww++) v += red[threadIdx.x][ww];
        red[threadIdx.x][0] = v * (1.f/8192.f);
    }
    __syncthreads();
    if (threadIdx.x == 0) {
        m[0]=red[0][0]; m[1]=red[1][0]; m[2]=red[2][0];
        cov[0][0]=red[3][0]-m[0]*m[0];
        cov[0][1]=cov[1][0]=red[4][0]-m[0]*m[1];
        cov[0][2]=cov[2][0]=red[5][0]-m[0]*m[2];
        cov[1][1]=red[6][0]-m[1]*m[1];
        cov[1][2]=cov[2][1]=red[7][0]-m[1]*m[2];
        cov[2][2]=red[8][0]-m[2]*m[2];
    }
    __syncthreads();
    if (threadIdx.x < 64) {
        int o = threadIdx.x;
        float wv0=w1[o*3], wv1=w1[o*3+1], wv2=w1[o*3+2];
        float mean = wv0*m[0]+wv1*m[1]+wv2*m[2] + b1[o];
        float var = wv0*wv0*cov[0][0] + wv1*wv1*cov[1][1] + wv2*wv2*cov[2][2]
                  + 2.f*(wv0*wv1*cov[0][1] + wv0*wv2*cov[0][2] + wv1*wv2*cov[1][2]);
        float sc = g1[o]*rsqrtf(var + BEPS);
        g_sc1[o] = sc;
        g_sh1[o] = be1[o] - mean*sc;
    }
}

// ---------------- conv1 + BN + relu ----------------
__global__ void k_conv1(const float* __restrict__ x, const float* __restrict__ w1,
                        const float* __restrict__ b1) {
    int n = blockIdx.x*256 + threadIdx.x;
    int b = blockIdx.y;
    float x0 = x[b*6144 + n], x1 = x[b*6144 + 2048 + n], x2 = x[b*6144 + 4096 + n];
    #pragma unroll 8
    for (int o=0;o<64;o++) {
        float pre = fmaf(w1[o*3], x0, fmaf(w1[o*3+1], x1, fmaf(w1[o*3+2], x2, b1[o])));
        float h = fmaf(g_sc1[o], pre, g_sh1[o]);
        g_h1[(b*64+o)*2048 + n] = fmaxf(h, 0.f);
    }
}

// ---------------- conv2: tiled GEMM 128o x 128n, K=64, pre-act + stats ----------
__global__ void __launch_bounds__(256) k_conv2(const float* __restrict__ w2,
                                               const float* __restrict__ b2) {
    __shared__ float As[32][128];   // As[k][o]
    __shared__ float Bs[32][128];   // Bs[k][n]
    __shared__ float s_sum[128], s_ss[128];
    int b = blockIdx.y, n0 = blockIdx.x*128, t = threadIdx.x;
    int tx = t & 15, ty = t >> 4;
    float acc[8][8];
    #pragma unroll
    for (int r=0;r<8;r++)
        #pragma unroll
        for (int c=0;c<8;c++) acc[r][c] = 0.f;
    if (t < 128) { s_sum[t] = 0.f; s_ss[t] = 0.f; }
    for (int kc = 0; kc < 64; kc += 32) {
        __syncthreads();
        #pragma unroll
        for (int i=0;i<16;i++) { int f=t+i*256; int k=f>>7, o=f&127; As[k][o] = w2[o*64 + kc + k]; }
        #pragma unroll
        for (int i=0;i<16;i++) { int f=t+i*256; int k=f>>7, n=f&127;
            Bs[k][n] = g_h1[(b*64 + kc + k)*2048 + n0 + n]; }
        __syncthreads();
        #pragma unroll
        for (int k=0;k<32;k++) {
            float a[8], bb[8];
            *(float4*)&a[0]  = *(const float4*)&As[k][ty*8];
            *(float4*)&a[4]  = *(const float4*)&As[k][ty*8+4];
            *(float4*)&bb[0] = *(const float4*)&Bs[k][tx*8];
            *(float4*)&bb[4] = *(const float4*)&Bs[k][tx*8+4];
            #pragma unroll
            for (int r=0;r<8;r++)
                #pragma unroll
                for (int c=0;c<8;c++) acc[r][c] = fmaf(a[r], bb[c], acc[r][c]);
        }
    }
    #pragma unroll
    for (int r=0;r<8;r++) {
        int o = ty*8 + r;
        float bias = b2[o];
        float rs = 0.f, rq = 0.f;
        float v[8];
        #pragma unroll
        for (int c=0;c<8;c++) { v[c] = acc[r][c] + bias; rs += v[c]; rq = fmaf(v[c], v[c], rq); }
        float* dst = &g_h2[(b*128+o)*2048 + n0 + tx*8];
        *(float4*)dst     = *(float4*)&v[0];
        *(float4*)(dst+4) = *(float4*)&v[4];
        atomicAdd(&s_sum[o], rs);
        atomicAdd(&s_ss[o], rq);
    }
    __syncthreads();
    if (t < 128) { atomicAdd(&g_c2sum[t], s_sum[t]); atomicAdd(&g_c2ss[t], s_ss[t]); }
}

__global__ void k_bn2fin(const float* __restrict__ g2, const float* __restrict__ be2) {
    int c = threadIdx.x;
    float mean = g_c2sum[c] * (1.f/8192.f);
    float var = g_c2ss[c] * (1.f/8192.f) - mean*mean;
    float sc = g2[c]*rsqrtf(var + BEPS);
    g_sc2[c] = sc;
    g_sh2[c] = be2[c] - mean*sc;
}

// ---------------- split w3 -> A' bf16 [row][hi|hi|lo] ----------------
__global__ void k_split_w3(const float* __restrict__ w3) {
    int id = blockIdx.x*256 + threadIdx.x;     // 2,097,152
    int row = id >> 7, k = id & 127;
    float v = w3[id];
    __nv_bfloat16 hi = __float2bfloat16(v);
    __nv_bfloat16 lo = __float2bfloat16(v - __bfloat162float(hi));
    __nv_bfloat16* dst = g_As + (size_t)row*384;
    dst[k] = hi; dst[128 + k] = hi; dst[256 + k] = lo;
}

// ---------------- BN2+relu, transpose h2 -> B' bf16 [col][hi|lo|hi] -------------
__global__ void __launch_bounds__(256) k_split_b() {
    __shared__ float smv[128][65];
    int b = blockIdx.y, n0 = blockIdx.x*64, t = threadIdx.x;
    #pragma unroll
    for (int i=0;i<32;i++) {
        int f = t + i*256; int c = f >> 6, n = f & 63;
        float v = g_h2[(b*128+c)*2048 + n0 + n];
        smv[c][n] = fmaxf(fmaf(g_sc2[c], v, g_sh2[c]), 0.f);
    }
    __syncthreads();
    int col = t & 63, q = t >> 6;               // q: channel group of 32
    __nv_bfloat16* dst = g_Bs + (size_t)(b*2048 + n0 + col)*384;
    #pragma unroll
    for (int ch=0; ch<32; ch++) {
        float v = smv[q*32+ch][col];
        __nv_bfloat16 hi = __float2bfloat16(v);
        __nv_bfloat16 lo = __float2bfloat16(v - __bfloat162float(hi));
        dst[q*32+ch] = hi;
        dst[128 + q*32+ch] = lo;
        dst[256 + q*32+ch] = hi;
    }
}

// ---------------- caps GEMM via WMMA bf16: D[16384x8192] = A' B'^T --------------
// CTA tile 128x128, 8 warps (4Mx2N), warp tile 32x64, K-chunk 32, double buffer.
// Epilogue: fragments -> smem -> per-row bias + sum/sumsq/max/min partial stats.
#define LDA 40                      // padded bf16 per smem row (80B, conflict-free)
#define ABUF_B 10240                // 128*40*2
#define EP_LD 132

__global__ void __launch_bounds__(256) k_caps_wmma(const float* __restrict__ b3) {
    extern __shared__ char sm[];
    __nv_bfloat16* Asm[2] = { (__nv_bfloat16*)sm, (__nv_bfloat16*)(sm + ABUF_B) };
    __nv_bfloat16* Bsm[2] = { (__nv_bfloat16*)(sm + 2*ABUF_B), (__nv_bfloat16*)(sm + 3*ABUF_B) };
    float* Ep = (float*)sm;         // 128 x 132 f32 (reused after mainloop)

    const int t = threadIdx.x, w = t >> 5;
    const int row0 = blockIdx.y * 128, col0 = blockIdx.x * 128;
    const int wm = (w >> 1) * 32, wn = (w & 1) * 64;
    const int r_ = t >> 2, j_ = t & 3;            // gmem->smem mapping helpers

    wmma::fragment<wmma::accumulator,16,16,16,float> acc[2][4];
    #pragma unroll
    for (int r=0;r<2;r++)
        #pragma unroll
        for (int c=0;c<4;c++) wmma::fill_fragment(acc[r][c], 0.f);

    const uint4* Ag = (const uint4*)g_As;
    const uint4* Bg = (const uint4*)g_Bs;

    // prologue: chunk 0
    {
        #pragma unroll
        for (int i=0;i<2;i++) {
            int idx = t + i*256; int r = idx>>2, j = idx&3;
            *(uint4*)(Asm[0] + r*LDA + j*8) = Ag[(size_t)(row0+r)*48 + j];
            *(uint4*)(Bsm[0] + r*LDA + j*8) = Bg[(size_t)(col0+r)*48 + j];
        }
    }
    __syncthreads();

    for (int kc = 0; kc < 12; kc++) {
        int cur = kc & 1;
        uint4 ra[2], rb[2];
        if (kc < 11) {
            int k4 = (kc+1)*4;     // uint4 offset of next chunk
            #pragma unroll
            for (int i=0;i<2;i++) {
                int idx = t + i*256; int r = idx>>2, j = idx&3;
                ra[i] = Ag[(size_t)(row0+r)*48 + k4 + j];
                rb[i] = Bg[(size_t)(col0+r)*48 + k4 + j];
            }
        }
        #pragma unroll
        for (int ks=0; ks<2; ks++) {
            wmma::fragment<wmma::matrix_a,16,16,16,__nv_bfloat16,wmma::row_major> af[2];
            wmma::fragment<wmma::matrix_b,16,16,16,__nv_bfloat16,wmma::col_major> bf[4];
            #pragma unroll
            for (int r=0;r<2;r++)
                wmma::load_matrix_sync(af[r], Asm[cur] + (wm + r*16)*LDA + ks*16, LDA);
            #pragma unroll
            for (int c=0;c<4;c++)
                wmma::load_matrix_sync(bf[c], Bsm[cur] + (wn + c*16)*LDA + ks*16, LDA);
            #pragma unroll
            for (int r=0;r<2;r++)
                #pragma unroll
                for (int c=0;c<4;c++)
                    wmma::mma_sync(acc[r][c], af[r], bf[c], acc[r][c]);
        }
        if (kc < 11) {
            int nxt = cur ^ 1;
            __syncthreads();
            #pragma unroll
            for (int i=0;i<2;i++) {
                int idx = t + i*256; int r = idx>>2, j = idx&3;
                *(uint4*)(Asm[nxt] + r*LDA + j*8) = ra[i];
                *(uint4*)(Bsm[nxt] + r*LDA + j*8) = rb[i];
            }
            __syncthreads();
        }
    }
    __syncthreads();

    // write fragments to smem
    #pragma unroll
    for (int r=0;r<2;r++)
        #pragma unroll
        for (int c=0;c<4;c++)
            wmma::store_matrix_sync(Ep + (wm + r*16)*EP_LD + wn + c*16, acc[r][c],
                                    EP_LD, wmma::mem_row_major);
    __syncthreads();

    // stats: thread pair (t, t^1) covers one row's 128 cols
    int row = t >> 1, half = t & 1;
    float bias = b3[row0 + row];
    const float* pr = Ep + row*EP_LD + half*64;
    float s = 0.f, q = 0.f, mx = -3.4028235e38f, mn = 3.4028235e38f;
    #pragma unroll
    for (int c=0;c<64;c++) {
        float v = pr[c] + bias;
        s += v; q = fmaf(v, v, q);
        mx = fmaxf(mx, v); mn = fminf(mn, v);
    }
    s  += __shfl_xor_sync(0xffffffffu, s, 1);
    q  += __shfl_xor_sync(0xffffffffu, q, 1);
    mx = fmaxf(mx, __shfl_xor_sync(0xffffffffu, mx, 1));
    mn = fminf(mn, __shfl_xor_sync(0xffffffffu, mn, 1));
    if (half == 0) {
        int gi = (row0 + row)*64 + blockIdx.x;
        g_psum[gi] = s; g_pss[gi] = q; g_pmx[gi] = mx; g_pmn[gi] = mn;
    }
}

// ---------------- reduce partial stats -> rowstats ----------------
__global__ void k_redstats() {
    int row = blockIdx.x*256 + threadIdx.x;    // 16384 rows
    float s = 0.f, q = 0.f;
    float mx[4], mn[4];
    #pragma unroll
    for (int b=0;b<4;b++) { mx[b] = -3.4028235e38f; mn[b] = 3.4028235e38f; }
    #pragma unroll
    for (int nt=0; nt<64; nt++) {
        int gi = row*64 + nt, b = nt >> 4;
        s += g_psum[gi]; q += g_pss[gi];
        mx[b] = fmaxf(mx[b], g_pmx[gi]);
        mn[b] = fminf(mn[b], g_pmn[gi]);
    }
    float* o = g_rowstats + row*10;
    o[0] = s; o[1] = q;
    #pragma unroll
    for (int b=0;b<4;b++) { o[2+b] = mx[b]; o[6+b] = mn[b]; }
}

// ---------------- finalize BN + max + squash -> u[b][p][q] ----------------
__global__ void k_ufin(const float* __restrict__ g3, const float* __restrict__ be3) {
    int idx = blockIdx.x*256 + threadIdx.x;   // 4096 (b,p)
    int b = idx >> 10, p = idx & 1023;
    float vq[16]; float sn = 0.f;
    #pragma unroll
    for (int q=0;q<16;q++) {
        int row = q*1024 + p;
        const float* st = g_rowstats + row*10;
        float mean = st[0]*(1.f/8192.f);
        float var  = st[1]*(1.f/8192.f) - mean*mean;
        float sc = g3[row]*rsqrtf(var + BEPS);
        float m = (sc >= 0.f) ? st[2+b] : st[6+b];   // BN affine is monotone
        float v = fmaf(sc, m - mean, be3[row]);
        vq[q] = v; sn = fmaf(v,v,sn);
    }
    float coef = sn/((1.f+sn)*sqrtf(sn));
    #pragma unroll
    for (int q=0;q<16;q++) g_u[(b*1024+p)*16 + q] = coef*vq[q];
}

// ---------------- u_hat = einsum(lpvq,bpq->blpv) ----------------
__global__ void k_uhat(const float* __restrict__ Wr) {
    int bid = blockIdx.x;                 // 16384: l, group of 4 p
    int l = bid >> 8, p0 = (bid & 255)*4;
    int t = threadIdx.x, pi = t >> 6, v = t & 63;
    int p = p0 + pi;
    __shared__ float us[4][4][16];        // [pi][b][q]
    { int pp = t>>6, bb=(t>>4)&3, q=t&15;
      us[pp][bb][q] = g_u[(bb*1024 + p0+pp)*16 + q]; }
    __syncthreads();
    const float* wr = Wr + (((long)(l*1024+p))*64 + v)*16;
    float4 a0 = *(const float4*)wr,     a1 = *(const float4*)(wr+4);
    float4 a2 = *(const float4*)(wr+8), a3 = *(const float4*)(wr+12);
    #pragma unroll
    for (int b=0;b<4;b++) {
        const float* u = us[pi][b];
        float d = a0.x*u[0]+a0.y*u[1]+a0.z*u[2]+a0.w*u[3]
                + a1.x*u[4]+a1.y*u[5]+a1.z*u[6]+a1.w*u[7]
                + a2.x*u[8]+a2.y*u[9]+a2.z*u[10]+a2.w*u[11]
                + a3.x*u[12]+a3.y*u[13]+a3.z*u[14]+a3.w*u[15];
        g_uhat[(((long)(b*64+l))*1024+p)*64 + v] = d;
    }
}

// ---------------- routing: softmax over L ----------------
__global__ void k_softmax() {
    int idx = blockIdx.x*256 + threadIdx.x;  // 4096 (b,p)
    int b = idx >> 10, p = idx & 1023;
    const float* bp = g_bij + b*65536 + p;
    float e[64]; float mx = -3.4e38f;
    #pragma unroll
    for (int l=0;l<64;l++){ e[l] = bp[l*1024]; mx = fmaxf(mx, e[l]); }
    float s = 0.f;
    #pragma unroll
    for (int l=0;l<64;l++){ e[l] = __expf(e[l]-mx); s += e[l]; }
    float inv = 1.f/s;
    float* cp = g_cij + b*65536 + p;
    #pragma unroll
    for (int l=0;l<64;l++) cp[l*1024] = e[l]*inv;
}

// ---------------- routing: v_j = squash(sum_p c*u_hat) ----------------
__global__ void k_vj() {
    int bid = blockIdx.x;                 // 256 (b,l)
    int b = bid >> 6, l = bid & 63;
    int t = threadIdx.x, v = t & 63, pc = t >> 6;
    __shared__ float cs[1024];
    __shared__ float red[4][64];
    __shared__ float sq[64];
    __shared__ float s_coef;
    for (int i=t;i<1024;i+=256) cs[i] = g_cij[(b*64+l)*1024 + i];
    __syncthreads();
    const float* uh = g_uhat + ((long)(b*64+l))*65536;
    float acc = 0.f;
    #pragma unroll 8
    for (int p = pc*256; p < pc*256+256; p++)
        acc = fmaf(cs[p], uh[p*64 + v], acc);
    red[pc][v] = acc;
    __syncthreads();
    if (t < 64) {
        float vr = red[0][t]+red[1][t]+red[2][t]+red[3][t];
        red[0][t] = vr;
        sq[t] = vr*vr;
    }
    __syncthreads();
    if (t == 0) {
        float sn = 0.f;
        for (int i=0;i<64;i++) sn += sq[i];
        s_coef = sn/((1.f+sn)*sqrtf(sn));
    }
    __syncthreads();
    if (t < 64) g_vj[(b*64+l)*64 + t] = s_coef*red[0][t];
}

// ---------------- routing: b_ij += <v_j, u_hat> ----------------
__global__ void k_bupd() {
    int bid = blockIdx.x;
    int b = bid >> 6, l = bid & 63;
    int t = threadIdx.x, lane = t & 31, w = t >> 5;
    __shared__ float vs[64];
    if (t < 64) vs[t] = g_vj[(b*64+l)*64 + t];
    __syncthreads();
    float v0 = vs[lane], v1 = vs[lane+32];
    const float* uh = g_uhat + ((long)(b*64+l))*65536;
    float* bp = g_bij + (b*64+l)*1024;
    for (int p = w; p < 1024; p += 8) {
        float d = fmaf(v0, uh[p*64+lane], v1*uh[p*64+lane+32]);
        #pragma unroll
        for (int off=16;off>0;off>>=1) d += __shfl_down_sync(0xffffffffu, d, off);
        if (lane==0) bp[p] += d;
    }
}

// ---------------- head: logits + presence ----------------
__global__ void k_logits(const float* __restrict__ fcw, const float* __restrict__ fcb,
                         float* __restrict__ out) {
    int bid = blockIdx.x;                 // 160 = 4*40
    int b = bid/40, o = bid%40;
    int t = threadIdx.x;                  // 128
    const float* vj = g_vj + b*4096;
    const float* wr = fcw + o*4096;
    float acc = 0.f;
    for (int i=t;i<4096;i+=128) acc = fmaf(vj[i], wr[i], acc);
    __shared__ float red[4];
    #pragma unroll
    for (int off=16;off>0;off>>=1) acc += __shfl_down_sync(0xffffffffu, acc, off);
    if ((t&31)==0) red[t>>5]=acc;
    __syncthreads();
    if (t==0) out[b*40+o] = red[0]+red[1]+red[2]+red[3] + fcb[o];
}

__global__ void k_pres(float* __restrict__ out) {
    int t = threadIdx.x;                  // 256 = (b,l)
    const float* vj = g_vj + t*64;
    float s = 0.f;
    #pragma unroll
    for (int i=0;i<64;i++) s = fmaf(vj[i], vj[i], s);
    out[160 + t] = sqrtf(s);
}

// ---------------- launch ----------------
extern "C" void kernel_launch(void* const* d_in, const int* in_sizes, int n_in,
                              void* d_out, int out_size) {
    const float* x   = (const float*)d_in[0];
    const float* w1  = (const float*)d_in[1];
    const float* b1  = (const float*)d_in[2];
    const float* g1  = (const float*)d_in[3];
    const float* be1 = (const float*)d_in[4];
    const float* w2  = (const float*)d_in[5];
    const float* b2  = (const float*)d_in[6];
    const float* g2  = (const float*)d_in[7];
    const float* be2 = (const float*)d_in[8];
    const float* w3  = (const float*)d_in[9];
    const float* b3  = (const float*)d_in[10];
    const float* g3  = (const float*)d_in[11];
    const float* be3 = (const float*)d_in[12];
    const float* Wr  = (const float*)d_in[13];
    const float* fcw = (const float*)d_in[14];
    const float* fcb = (const float*)d_in[15];
    float* out = (float*)d_out;

    const int caps_smem = 128*EP_LD*4;   // 67584 > 4*ABUF_B
    cudaFuncSetAttribute(k_caps_wmma, cudaFuncAttributeMaxDynamicSharedMemorySize, caps_smem);

    k_zero<<<1024,256>>>();
    k_split_w3<<<8192,256>>>(w3);
    k_bn1<<<1,256>>>(x,w1,b1,g1,be1);
    k_conv1<<<dim3(8,4),256>>>(x,w1,b1);
    k_conv2<<<dim3(16,4),256>>>(w2,b2);
    k_bn2fin<<<1,128>>>(g2,be2);
    k_split_b<<<dim3(32,4),256>>>();
    k_caps_wmma<<<dim3(64,128),256,caps_smem>>>(b3);
    k_redstats<<<64,256>>>();
    k_ufin<<<16,256>>>(g3,be3);
    k_uhat<<<16384,256>>>(Wr);
    for (int it=0; it<3; it++) {
        k_softmax<<<16,256>>>();
        k_vj<<<256,256>>>();
        if (it<2) k_bupd<<<256,256>>>();
    }
    k_logits<<<160,128>>>(fcw, fcb, out);
    k_pres<<<1,256>>>(out);
}

// round 5
// speedup vs baseline: 2.8918x; 1.0854x over previous
#include <cuda_runtime.h>
#include <cuda_bf16.h>
#include <mma.h>
#include <cstdint>
#include <math.h>

using namespace nvcuda;

#define BEPS 1e-5f

// ---------------- scratch (static device globals; no allocation) ----------------
__device__ float g_h1[4*64*2048];            // conv1 output (post BN+relu)
__device__ float g_h2[4*128*2048];           // conv2 pre-act
__device__ float g_sc1[64], g_sh1[64];
__device__ float g_c2sum[128], g_c2ss[128];
__device__ float g_sc2[128], g_sh2[128];
__device__ __align__(16) __nv_bfloat16 g_As[16384*384];  // A' = [hi|hi|lo]
__device__ __align__(16) __nv_bfloat16 g_Bs[8192*384];   // B' = [hi|lo|hi]
__device__ float g_psum[16384*32], g_pss[16384*32], g_pmx[16384*32], g_pmn[16384*32];
__device__ float g_rowstats[16384*10];       // per (q,p): sum, sumsq, max[4], min[4]
__device__ float g_u[4*1024*16];             // squashed primary caps [b][p][q]
__device__ float g_uhat[(long)4*64*1024*64]; // 67MB [b][l][p][v]
__device__ float g_bij[4*64*1024];
__device__ float g_cij[4*64*1024];
__device__ float g_vj[4*64*64];

__device__ __forceinline__ uint32_t smem_u32(const void* p) {
    uint32_t a;
    asm("{ .reg .u64 t; cvta.to.shared.u64 t, %1; cvt.u32.u64 %0, t; }" : "=r"(a) : "l"(p));
    return a;
}
__device__ __forceinline__ void cp16(uint32_t dst, const void* src) {
    asm volatile("cp.async.cg.shared.global [%0], [%1], 16;" :: "r"(dst), "l"(src));
}
#define CP_COMMIT() asm volatile("cp.async.commit_group;" ::: "memory")
#define CP_WAIT(n)  asm volatile("cp.async.wait_group %0;" :: "n"(n) : "memory")

// ---------------- zero the accumulators that need it each launch ----------------
__global__ void k_zero() {
    int i = blockIdx.x*256 + threadIdx.x;
    if (i < 4*64*1024) g_bij[i] = 0.f;
    if (i < 128) { g_c2sum[i] = 0.f; g_c2ss[i] = 0.f; }
}

// ---------------- BN1 params from analytic stats of x (linear layer) ------------
__global__ void k_bn1(const float* __restrict__ x, const float* __restrict__ w1,
                      const float* __restrict__ b1, const float* __restrict__ g1,
                      const float* __restrict__ be1) {
    float s0=0,s1=0,s2=0,p00=0,p01=0,p02=0,p11=0,p12=0,p22=0;
    for (int i = threadIdx.x; i < 8192; i += 256) {
        int b = i >> 11, n = i & 2047;
        const float* xb = x + b*3*2048 + n;
        float a = xb[0], c = xb[2048], d = xb[4096];
        s0+=a; s1+=c; s2+=d;
        p00+=a*a; p01+=a*c; p02+=a*d; p11+=c*c; p12+=c*d; p22+=d*d;
    }
    __shared__ float red[9][8];
    __shared__ float m[3], cov[3][3];
    float vals[9] = {s0,s1,s2,p00,p01,p02,p11,p12,p22};
    int lane = threadIdx.x & 31, w = threadIdx.x >> 5;
    #pragma unroll
    for (int j=0;j<9;j++) {
        float v = vals[j];
        #pragma unroll
        for (int o=16;o>0;o>>=1) v += __shfl_down_sync(0xffffffffu, v, o);
        if (lane==0) red[j][w] = v;
    }
    __syncthreads();
    if (threadIdx.x < 9) {
        float v = 0;
        for (int ww=0; ww<8; ww++) v += red[threadIdx.x][ww];
        red[threadIdx.x][0] = v * (1.f/8192.f);
    }
    __syncthreads();
    if (threadIdx.x == 0) {
        m[0]=red[0][0]; m[1]=red[1][0]; m[2]=red[2][0];
        cov[0][0]=red[3][0]-m[0]*m[0];
        cov[0][1]=cov[1][0]=red[4][0]-m[0]*m[1];
        cov[0][2]=cov[2][0]=red[5][0]-m[0]*m[2];
        cov[1][1]=red[6][0]-m[1]*m[1];
        cov[1][2]=cov[2][1]=red[7][0]-m[1]*m[2];
        cov[2][2]=red[8][0]-m[2]*m[2];
    }
    __syncthreads();
    if (threadIdx.x < 64) {
        int o = threadIdx.x;
        float wv0=w1[o*3], wv1=w1[o*3+1], wv2=w1[o*3+2];
        float mean = wv0*m[0]+wv1*m[1]+wv2*m[2] + b1[o];
        float var = wv0*wv0*cov[0][0] + wv1*wv1*cov[1][1] + wv2*wv2*cov[2][2]
                  + 2.f*(wv0*wv1*cov[0][1] + wv0*wv2*cov[0][2] + wv1*wv2*cov[1][2]);
        float sc = g1[o]*rsqrtf(var + BEPS);
        g_sc1[o] = sc;
        g_sh1[o] = be1[o] - mean*sc;
    }
}

// ---------------- conv1 + BN + relu ----------------
__global__ void k_conv1(const float* __restrict__ x, const float* __restrict__ w1,
                        const float* __restrict__ b1) {
    int n = blockIdx.x*256 + threadIdx.x;
    int b = blockIdx.y;
    int og = blockIdx.z*16;
    float x0 = x[b*6144 + n], x1 = x[b*6144 + 2048 + n], x2 = x[b*6144 + 4096 + n];
    #pragma unroll
    for (int oo=0;oo<16;oo++) {
        int o = og + oo;
        float pre = fmaf(w1[o*3], x0, fmaf(w1[o*3+1], x1, fmaf(w1[o*3+2], x2, b1[o])));
        float h = fmaf(g_sc1[o], pre, g_sh1[o]);
        g_h1[(b*64+o)*2048 + n] = fmaxf(h, 0.f);
    }
}

// ---------------- conv2: tiled GEMM 128o x 128n, K=64, pre-act + stats ----------
__global__ void __launch_bounds__(256) k_conv2(const float* __restrict__ w2,
                                               const float* __restrict__ b2) {
    __shared__ float As[32][128];   // As[k][o]
    __shared__ float Bs[32][128];   // Bs[k][n]
    __shared__ float s_sum[128], s_ss[128];
    int b = blockIdx.y, n0 = blockIdx.x*128, t = threadIdx.x;
    int tx = t & 15, ty = t >> 4;
    float acc[8][8];
    #pragma unroll
    for (int r=0;r<8;r++)
        #pragma unroll
        for (int c=0;c<8;c++) acc[r][c] = 0.f;
    if (t < 128) { s_sum[t] = 0.f; s_ss[t] = 0.f; }
    for (int kc = 0; kc < 64; kc += 32) {
        __syncthreads();
        #pragma unroll
        for (int i=0;i<16;i++) { int f=t+i*256; int k=f>>7, o=f&127; As[k][o] = w2[o*64 + kc + k]; }
        #pragma unroll
        for (int i=0;i<16;i++) { int f=t+i*256; int k=f>>7, n=f&127;
            Bs[k][n] = g_h1[(b*64 + kc + k)*2048 + n0 + n]; }
        __syncthreads();
        #pragma unroll
        for (int k=0;k<32;k++) {
            float a[8], bb[8];
            *(float4*)&a[0]  = *(const float4*)&As[k][ty*8];
            *(float4*)&a[4]  = *(const float4*)&As[k][ty*8+4];
            *(float4*)&bb[0] = *(const float4*)&Bs[k][tx*8];
            *(float4*)&bb[4] = *(const float4*)&Bs[k][tx*8+4];
            #pragma unroll
            for (int r=0;r<8;r++)
                #pragma unroll
                for (int c=0;c<8;c++) acc[r][c] = fmaf(a[r], bb[c], acc[r][c]);
        }
    }
    #pragma unroll
    for (int r=0;r<8;r++) {
        int o = ty*8 + r;
        float bias = b2[o];
        float rs = 0.f, rq = 0.f;
        float v[8];
        #pragma unroll
        for (int c=0;c<8;c++) { v[c] = acc[r][c] + bias; rs += v[c]; rq = fmaf(v[c], v[c], rq); }
        float* dst = &g_h2[(b*128+o)*2048 + n0 + tx*8];
        *(float4*)dst     = *(float4*)&v[0];
        *(float4*)(dst+4) = *(float4*)&v[4];
        atomicAdd(&s_sum[o], rs);
        atomicAdd(&s_ss[o], rq);
    }
    __syncthreads();
    if (t < 128) { atomicAdd(&g_c2sum[t], s_sum[t]); atomicAdd(&g_c2ss[t], s_ss[t]); }
}

__global__ void k_bn2fin(const float* __restrict__ g2, const float* __restrict__ be2) {
    int c = threadIdx.x;
    float mean = g_c2sum[c] * (1.f/8192.f);
    float var = g_c2ss[c] * (1.f/8192.f) - mean*mean;
    float sc = g2[c]*rsqrtf(var + BEPS);
    g_sc2[c] = sc;
    g_sh2[c] = be2[c] - mean*sc;
}

// ---------------- split w3 -> A' bf16 [row][hi|hi|lo] ----------------
__global__ void k_split_w3(const float* __restrict__ w3) {
    int id = blockIdx.x*256 + threadIdx.x;     // 2,097,152
    int row = id >> 7, k = id & 127;
    float v = w3[id];
    __nv_bfloat16 hi = __float2bfloat16(v);
    __nv_bfloat16 lo = __float2bfloat16(v - __bfloat162float(hi));
    __nv_bfloat16* dst = g_As + (size_t)row*384;
    dst[k] = hi; dst[128 + k] = hi; dst[256 + k] = lo;
}

// ---------------- BN2+relu, transpose h2 -> B' bf16 [col][hi|lo|hi] -------------
__global__ void __launch_bounds__(256) k_split_b() {
    __shared__ float smv[128][65];
    int b = blockIdx.y, n0 = blockIdx.x*64, t = threadIdx.x;
    #pragma unroll
    for (int i=0;i<32;i++) {
        int f = t + i*256; int c = f >> 6, n = f & 63;
        float v = g_h2[(b*128+c)*2048 + n0 + n];
        smv[c][n] = fmaxf(fmaf(g_sc2[c], v, g_sh2[c]), 0.f);
    }
    __syncthreads();
    int col = t & 63, q = t >> 6;               // q: channel group of 32
    __nv_bfloat16* dst = g_Bs + (size_t)(b*2048 + n0 + col)*384;
    #pragma unroll
    for (int ch=0; ch<32; ch++) {
        float v = smv[q*32+ch][col];
        __nv_bfloat16 hi = __float2bfloat16(v);
        __nv_bfloat16 lo = __float2bfloat16(v - __bfloat162float(hi));
        dst[q*32+ch] = hi;
        dst[128 + q*32+ch] = lo;
        dst[256 + q*32+ch] = hi;
    }
}

// ---------------- caps GEMM via WMMA bf16: D[16384x8192] = A' B'^T --------------
// CTA tile 128(M) x 256(N), 8 warps (2Mx4N), warp tile 64x64 (4x4 frags).
// K = 384, chunks of 32, 3-stage cp.async pipeline.
// Epilogue: two half passes through 128x132 smem; per-row bias+sum/sumsq/max/min.
#define LDA 40
#define A_ST 10240                  // 128*40*2
#define B_ST 20480                  // 256*40*2
#define STG (A_ST + B_ST)           // 30720
#define CAPS_SMEM (3*STG)           // 92160
#define EP_LD 132

__global__ void __launch_bounds__(256) k_caps_wmma(const float* __restrict__ b3) {
    extern __shared__ char sm[];
    const uint32_t sb = smem_u32(sm);
    const int t = threadIdx.x, w = t >> 5;
    const int row0 = blockIdx.y * 128, col0 = blockIdx.x * 256;
    const int wm = (w >> 2) * 64, wn = (w & 3) * 64;

    wmma::fragment<wmma::accumulator,16,16,16,float> acc[4][4];
    #pragma unroll
    for (int r=0;r<4;r++)
        #pragma unroll
        for (int c=0;c<4;c++) wmma::fill_fragment(acc[r][c], 0.f);

    const int ar = t >> 1, aj = t & 1;          // A: 128 rows x 2 cp16 (512 / 256thr)
    const int br = t >> 2, bj = t & 3;          // B: 256 rows x 4... wait 256*4=1024/256=4
    // A chunk: 128 rows * 64B = 512 x16B -> 2 per thread
    // B chunk: 256 rows * 64B = 1024 x16B -> 4 per thread

    auto issue = [&](int stage, int kc) {
        uint32_t ab = sb + stage*STG;
        uint32_t bb = ab + A_ST;
        #pragma unroll
        for (int i=0;i<2;i++) {
            int idx = t + i*256; int r = idx >> 2, j = idx & 3;
            cp16(ab + (uint32_t)(r*LDA + j*8)*2,
                 g_As + (size_t)(row0 + r)*384 + kc*32 + j*8);
        }
        #pragma unroll
        for (int i=0;i<4;i++) {
            int idx = t + i*256; int r = idx >> 2, j = idx & 3;
            cp16(bb + (uint32_t)(r*LDA + j*8)*2,
                 g_Bs + (size_t)(col0 + r)*384 + kc*32 + j*8);
        }
        CP_COMMIT();
    };

    issue(0, 0);
    issue(1, 1);

    for (int kc = 0; kc < 12; kc++) {
        if (kc < 11) { CP_WAIT(1); } else { CP_WAIT(0); }
        __syncthreads();
        if (kc + 2 < 12) issue((kc+2)%3, kc+2);
        const __nv_bfloat16* Asm = (const __nv_bfloat16*)(sm + (kc%3)*STG);
        const __nv_bfloat16* Bsm = (const __nv_bfloat16*)(sm + (kc%3)*STG + A_ST);
        #pragma unroll
        for (int ks=0; ks<2; ks++) {
            wmma::fragment<wmma::matrix_a,16,16,16,__nv_bfloat16,wmma::row_major> af[4];
            wmma::fragment<wmma::matrix_b,16,16,16,__nv_bfloat16,wmma::col_major> bf[4];
            #pragma unroll
            for (int r=0;r<4;r++)
                wmma::load_matrix_sync(af[r], Asm + (wm + r*16)*LDA + ks*16, LDA);
            #pragma unroll
            for (int c=0;c<4;c++)
                wmma::load_matrix_sync(bf[c], Bsm + (wn + c*16)*LDA + ks*16, LDA);
            #pragma unroll
            for (int r=0;r<4;r++)
                #pragma unroll
                for (int c=0;c<4;c++)
                    wmma::mma_sync(acc[r][c], af[r], bf[c], acc[r][c]);
        }
    }
    __syncthreads();

    // epilogue: two half passes (N cols 0..127, 128..255)
    float* Ep = (float*)sm;
    int row = t >> 1, half = t & 1;
    float bias = b3[row0 + row];
    float s = 0.f, q = 0.f, mx = -3.4028235e38f, mn = 3.4028235e38f;
    #pragma unroll
    for (int h=0; h<2; h++) {
        __syncthreads();
        if ((wn >= 128 ? 1 : 0) == h) {
            #pragma unroll
            for (int r=0;r<4;r++)
                #pragma unroll
                for (int c=0;c<4;c++)
                    wmma::store_matrix_sync(Ep + (wm + r*16)*EP_LD + (wn & 127) + c*16,
                                            acc[r][c], EP_LD, wmma::mem_row_major);
        }
        __syncthreads();
        const float* pr = Ep + row*EP_LD + half*64;
        #pragma unroll
        for (int c=0;c<64;c++) {
            float v = pr[c] + bias;
            s += v; q = fmaf(v, v, q);
            mx = fmaxf(mx, v); mn = fminf(mn, v);
        }
    }
    s  += __shfl_xor_sync(0xffffffffu, s, 1);
    q  += __shfl_xor_sync(0xffffffffu, q, 1);
    mx = fmaxf(mx, __shfl_xor_sync(0xffffffffu, mx, 1));
    mn = fminf(mn, __shfl_xor_sync(0xffffffffu, mn, 1));
    if (half == 0) {
        int gi = (row0 + row)*32 + blockIdx.x;
        g_psum[gi] = s; g_pss[gi] = q; g_pmx[gi] = mx; g_pmn[gi] = mn;
    }
}

// ---------------- reduce partial stats -> rowstats ----------------
__global__ void k_redstats() {
    int row = blockIdx.x*256 + threadIdx.x;    // 16384 rows
    float s = 0.f, q = 0.f;
    float mx[4], mn[4];
    #pragma unroll
    for (int b=0;b<4;b++) { mx[b] = -3.4028235e38f; mn[b] = 3.4028235e38f; }
    #pragma unroll
    for (int nt=0; nt<32; nt++) {
        int gi = row*32 + nt, b = nt >> 3;
        s += g_psum[gi]; q += g_pss[gi];
        mx[b] = fmaxf(mx[b], g_pmx[gi]);
        mn[b] = fminf(mn[b], g_pmn[gi]);
    }
    float* o = g_rowstats + row*10;
    o[0] = s; o[1] = q;
    #pragma unroll
    for (int b=0;b<4;b++) { o[2+b] = mx[b]; o[6+b] = mn[b]; }
}

// ---------------- finalize BN + max + squash -> u[b][p][q] ----------------
__global__ void k_ufin(const float* __restrict__ g3, const float* __restrict__ be3) {
    int idx = blockIdx.x*256 + threadIdx.x;   // 4096 (b,p)
    int b = idx >> 10, p = idx & 1023;
    float vq[16]; float sn = 0.f;
    #pragma unroll
    for (int q=0;q<16;q++) {
        int row = q*1024 + p;
        const float* st = g_rowstats + row*10;
        float mean = st[0]*(1.f/8192.f);
        float var  = st[1]*(1.f/8192.f) - mean*mean;
        float sc = g3[row]*rsqrtf(var + BEPS);
        float m = (sc >= 0.f) ? st[2+b] : st[6+b];   // BN affine is monotone
        float v = fmaf(sc, m - mean, be3[row]);
        vq[q] = v; sn = fmaf(v,v,sn);
    }
    float coef = sn/((1.f+sn)*sqrtf(sn));
    #pragma unroll
    for (int q=0;q<16;q++) g_u[(b*1024+p)*16 + q] = coef*vq[q];
}

// ---------------- u_hat = einsum(lpvq,bpq->blpv) ----------------
__global__ void k_uhat(const float* __restrict__ Wr) {
    int bid = blockIdx.x;                 // 16384: l, group of 4 p
    int l = bid >> 8, p0 = (bid & 255)*4;
    int t = threadIdx.x, pi = t >> 6, v = t & 63;
    int p = p0 + pi;
    __shared__ float us[4][4][16];        // [pi][b][q]
    { int pp = t>>6, bb=(t>>4)&3, q=t&15;
      us[pp][bb][q] = g_u[(bb*1024 + p0+pp)*16 + q]; }
    __syncthreads();
    const float* wr = Wr + (((long)(l*1024+p))*64 + v)*16;
    float4 a0 = *(const float4*)wr,     a1 = *(const float4*)(wr+4);
    float4 a2 = *(const float4*)(wr+8), a3 = *(const float4*)(wr+12);
    #pragma unroll
    for (int b=0;b<4;b++) {
        const float* u = us[pi][b];
        float d = a0.x*u[0]+a0.y*u[1]+a0.z*u[2]+a0.w*u[3]
                + a1.x*u[4]+a1.y*u[5]+a1.z*u[6]+a1.w*u[7]
                + a2.x*u[8]+a2.y*u[9]+a2.z*u[10]+a2.w*u[11]
                + a3.x*u[12]+a3.y*u[13]+a3.z*u[14]+a3.w*u[15];
        g_uhat[(((long)(b*64+l))*1024+p)*64 + v] = d;
    }
}

// ---------------- routing: softmax over L ----------------
__global__ void k_softmax() {
    int idx = blockIdx.x*256 + threadIdx.x;  // 4096 (b,p)
    int b = idx >> 10, p = idx & 1023;
    const float* bp = g_bij + b*65536 + p;
    float e[64]; float mx = -3.4e38f;
    #pragma unroll
    for (int l=0;l<64;l++){ e[l] = bp[l*1024]; mx = fmaxf(mx, e[l]); }
    float s = 0.f;
    #pragma unroll
    for (int l=0;l<64;l++){ e[l] = __expf(e[l]-mx); s += e[l]; }
    float inv = 1.f/s;
    float* cp = g_cij + b*65536 + p;
    #pragma unroll
    for (int l=0;l<64;l++) cp[l*1024] = e[l]*inv;
}

// ---------------- routing: v_j = squash(sum_p c*u_hat) ----------------
__global__ void k_vj() {
    int bid = blockIdx.x;                 // 256 (b,l)
    int b = bid >> 6, l = bid & 63;
    int t = threadIdx.x, v = t & 63, pc = t >> 6;
    __shared__ float cs[1024];
    __shared__ float red[4][64];
    __shared__ float sq[64];
    __shared__ float s_coef;
    for (int i=t;i<1024;i+=256) cs[i] = g_cij[(b*64+l)*1024 + i];
    __syncthreads();
    const float* uh = g_uhat + ((long)(b*64+l))*65536;
    float acc = 0.f;
    #pragma unroll 8
    for (int p = pc*256; p < pc*256+256; p++)
        acc = fmaf(cs[p], uh[p*64 + v], acc);
    red[pc][v] = acc;
    __syncthreads();
    if (t < 64) {
        float vr = red[0][t]+red[1][t]+red[2][t]+red[3][t];
        red[0][t] = vr;
        sq[t] = vr*vr;
    }
    __syncthreads();
    if (t == 0) {
        float sn = 0.f;
        for (int i=0;i<64;i++) sn += sq[i];
        s_coef = sn/((1.f+sn)*sqrtf(sn));
    }
    __syncthreads();
    if (t < 64) g_vj[(b*64+l)*64 + t] = s_coef*red[0][t];
}

// ---------------- routing: b_ij += <v_j, u_hat> ----------------
__global__ void k_bupd() {
    int bid = blockIdx.x;
    int b = bid >> 6, l = bid & 63;
    int t = threadIdx.x, lane = t & 31, w = t >> 5;
    __shared__ float vs[64];
    if (t < 64) vs[t] = g_vj[(b*64+l)*64 + t];
    __syncthreads();
    float v0 = vs[lane], v1 = vs[lane+32];
    const float* uh = g_uhat + ((long)(b*64+l))*65536;
    float* bp = g_bij + (b*64+l)*1024;
    for (int p = w; p < 1024; p += 8) {
        float d = fmaf(v0, uh[p*64+lane], v1*uh[p*64+lane+32]);
        #pragma unroll
        for (int off=16;off>0;off>>=1) d += __shfl_down_sync(0xffffffffu, d, off);
        if (lane==0) bp[p] += d;
    }
}

// ---------------- head: logits + presence ----------------
__global__ void k_logits(const float* __restrict__ fcw, const float* __restrict__ fcb,
                         float* __restrict__ out) {
    int bid = blockIdx.x;                 // 160 = 4*40
    int b = bid/40, o = bid%40;
    int t = threadIdx.x;                  // 128
    const float* vj = g_vj + b*4096;
    const float* wr = fcw + o*4096;
    float acc = 0.f;
    for (int i=t;i<4096;i+=128) acc = fmaf(vj[i], wr[i], acc);
    __shared__ float red[4];
    #pragma unroll
    for (int off=16;off>0;off>>=1) acc += __shfl_down_sync(0xffffffffu, acc, off);
    if ((t&31)==0) red[t>>5]=acc;
    __syncthreads();
    if (t==0) out[b*40+o] = red[0]+red[1]+red[2]+red[3] + fcb[o];
}

__global__ void k_pres(float* __restrict__ out) {
    int t = threadIdx.x;                  // 256 = (b,l)
    const float* vj = g_vj + t*64;
    float s = 0.f;
    #pragma unroll
    for (int i=0;i<64;i++) s = fmaf(vj[i], vj[i], s);
    out[160 + t] = sqrtf(s);
}

// ---------------- launch ----------------
extern "C" void kernel_launch(void* const* d_in, const int* in_sizes, int n_in,
                              void* d_out, int out_size) {
    const float* x   = (const float*)d_in[0];
    const float* w1  = (const float*)d_in[1];
    const float* b1  = (const float*)d_in[2];
    const float* g1  = (const float*)d_in[3];
    const float* be1 = (const float*)d_in[4];
    const float* w2  = (const float*)d_in[5];
    const float* b2  = (const float*)d_in[6];
    const float* g2  = (const float*)d_in[7];
    const float* be2 = (const float*)d_in[8];
    const float* w3  = (const float*)d_in[9];
    const float* b3  = (const float*)d_in[10];
    const float* g3  = (const float*)d_in[11];
    const float* be3 = (const float*)d_in[12];
    const float* Wr  = (const float*)d_in[13];
    const float* fcw = (const float*)d_in[14];
    const float* fcb = (const float*)d_in[15];
    float* out = (float*)d_out;

    cudaFuncSetAttribute(k_caps_wmma, cudaFuncAttributeMaxDynamicSharedMemorySize, CAPS_SMEM);

    k_zero<<<1024,256>>>();
    k_split_w3<<<8192,256>>>(w3);
    k_bn1<<<1,256>>>(x,w1,b1,g1,be1);
    k_conv1<<<dim3(8,4,4),256>>>(x,w1,b1);
    k_conv2<<<dim3(16,4),256>>>(w2,b2);
    k_bn2fin<<<1,128>>>(g2,be2);
    k_split_b<<<dim3(32,4),256>>>();
    k_caps_wmma<<<dim3(32,128),256,CAPS_SMEM>>>(b3);
    k_redstats<<<64,256>>>();
    k_ufin<<<16,256>>>(g3,be3);
    k_uhat<<<16384,256>>>(Wr);
    for (int it=0; it<3; it++) {
        k_softmax<<<16,256>>>();
        k_vj<<<256,256>>>();
        if (it<2) k_bupd<<<256,256>>>();
    }
    k_logits<<<160,128>>>(fcw, fcb, out);
    k_pres<<<1,256>>>(out);
}

// round 6
// speedup vs baseline: 3.7684x; 1.3031x over previous
#include <cuda_runtime.h>
#include <cuda_fp16.h>
#include <mma.h>
#include <cstdint>
#include <math.h>

using namespace nvcuda;

#define BEPS 1e-5f

// ---------------- scratch (static device globals; no allocation) ----------------
__device__ float g_h1[4*64*2048];            // conv1 output (post BN+relu)
__device__ float g_h2[4*128*2048];           // conv2 pre-act
__device__ float g_c2sum[128], g_c2ss[128];
__device__ __align__(16) __half g_As[16384*256];  // A' = [hi(128)|lo(128)] fp16
__device__ __align__(16) __half g_Bs[8192*128];   // B' = hi only, fp16
__device__ float g_psum[16384*32], g_pss[16384*32], g_pmx[16384*32], g_pmn[16384*32];
__device__ float g_rowstats[16384*10];       // per (q,p): sum, sumsq, max[4], min[4]
__device__ float g_u[4*1024*16];             // squashed primary caps [b][p][q]
__device__ float g_uhat[(long)4*64*1024*64]; // 67MB [b][l][p][v]
__device__ float g_bij[4*64*1024];
__device__ float g_cij[4*64*1024];
__device__ float g_vj[4*64*64];

__device__ __forceinline__ uint32_t smem_u32(const void* p) {
    uint32_t a;
    asm("{ .reg .u64 t; cvta.to.shared.u64 t, %1; cvt.u32.u64 %0, t; }" : "=r"(a) : "l"(p));
    return a;
}
__device__ __forceinline__ void cp16(uint32_t dst, const void* src) {
    asm volatile("cp.async.cg.shared.global [%0], [%1], 16;" :: "r"(dst), "l"(src));
}
#define CP_COMMIT() asm volatile("cp.async.commit_group;" ::: "memory")
#define CP_WAIT(n)  asm volatile("cp.async.wait_group %0;" :: "n"(n) : "memory")

// ---------------- front: conv1(+inline bn1) | split w3 | zero bij/c2 ----------
__global__ void __launch_bounds__(256) k_front(const float* __restrict__ x,
        const float* __restrict__ w1, const float* __restrict__ b1,
        const float* __restrict__ g1, const float* __restrict__ be1,
        const float* __restrict__ w3) {
    int blk = blockIdx.x, t = threadIdx.x;
    if (blk < 128) {
        // ---- conv1 block with per-block analytic BN1 ----
        int nb = blk & 7, b = (blk >> 3) & 3, og = (blk >> 5) * 16;
        __shared__ float red[9][8];
        __shared__ float m[3], cov[3][3];
        __shared__ float ssc[16], ssh[16];
        float s0=0,s1=0,s2=0,p00=0,p01=0,p02=0,p11=0,p12=0,p22=0;
        for (int i = t; i < 8192; i += 256) {
            int bb = i >> 11, n = i & 2047;
            const float* xb = x + bb*3*2048 + n;
            float a = xb[0], c = xb[2048], d = xb[4096];
            s0+=a; s1+=c; s2+=d;
            p00+=a*a; p01+=a*c; p02+=a*d; p11+=c*c; p12+=c*d; p22+=d*d;
        }
        float vals[9] = {s0,s1,s2,p00,p01,p02,p11,p12,p22};
        int lane = t & 31, w = t >> 5;
        #pragma unroll
        for (int j=0;j<9;j++) {
            float v = vals[j];
            #pragma unroll
            for (int o=16;o>0;o>>=1) v += __shfl_down_sync(0xffffffffu, v, o);
            if (lane==0) red[j][w] = v;
        }
        __syncthreads();
        if (t < 9) {
            float v = 0;
            for (int ww=0; ww<8; ww++) v += red[t][ww];
            red[t][0] = v * (1.f/8192.f);
        }
        __syncthreads();
        if (t == 0) {
            m[0]=red[0][0]; m[1]=red[1][0]; m[2]=red[2][0];
            cov[0][0]=red[3][0]-m[0]*m[0];
            cov[0][1]=cov[1][0]=red[4][0]-m[0]*m[1];
            cov[0][2]=cov[2][0]=red[5][0]-m[0]*m[2];
            cov[1][1]=red[6][0]-m[1]*m[1];
            cov[1][2]=cov[2][1]=red[7][0]-m[1]*m[2];
            cov[2][2]=red[8][0]-m[2]*m[2];
        }
        __syncthreads();
        if (t < 16) {
            int o = og + t;
            float wv0=w1[o*3], wv1=w1[o*3+1], wv2=w1[o*3+2];
            float mean = wv0*m[0]+wv1*m[1]+wv2*m[2] + b1[o];
            float var = wv0*wv0*cov[0][0] + wv1*wv1*cov[1][1] + wv2*wv2*cov[2][2]
                      + 2.f*(wv0*wv1*cov[0][1] + wv0*wv2*cov[0][2] + wv1*wv2*cov[1][2]);
            float sc = g1[o]*rsqrtf(var + BEPS);
            ssc[t] = sc;
            ssh[t] = be1[o] - mean*sc;
        }
        __syncthreads();
        int n = nb*256 + t;
        float x0 = x[b*6144 + n], x1 = x[b*6144 + 2048 + n], x2 = x[b*6144 + 4096 + n];
        #pragma unroll
        for (int oo=0;oo<16;oo++) {
            int o = og + oo;
            float pre = fmaf(w1[o*3], x0, fmaf(w1[o*3+1], x1, fmaf(w1[o*3+2], x2, b1[o])));
            float h = fmaf(ssc[oo], pre, ssh[oo]);
            g_h1[(b*64+o)*2048 + n] = fmaxf(h, 0.f);
        }
    } else if (blk < 2176) {
        // ---- split w3 -> fp16 hi/lo pairs ----
        int blk2 = blk - 128;
        #pragma unroll
        for (int i=0;i<4;i++) {
            int id = blk2*1024 + i*256 + t;
            int row = id >> 7, k = id & 127;
            float v = w3[id];
            __half hi = __float2half_rn(v);
            __half lo = __float2half_rn(v - __half2float(hi));
            g_As[(size_t)row*256 + k] = hi;
            g_As[(size_t)row*256 + 128 + k] = lo;
        }
    } else if (blk < 2432) {
        int blk3 = blk - 2176;
        #pragma unroll
        for (int i=0;i<4;i++) g_bij[blk3*1024 + i*256 + t] = 0.f;
    } else {
        if (t < 128) { g_c2sum[t] = 0.f; g_c2ss[t] = 0.f; }
    }
}

// ---------------- conv2: tiled GEMM 128o x 128n, K=64, pre-act + stats ----------
__global__ void __launch_bounds__(256) k_conv2(const float* __restrict__ w2,
                                               const float* __restrict__ b2) {
    __shared__ float As[32][128];   // As[k][o]
    __shared__ float Bs[32][128];   // Bs[k][n]
    __shared__ float s_sum[128], s_ss[128];
    int b = blockIdx.y, n0 = blockIdx.x*128, t = threadIdx.x;
    int tx = t & 15, ty = t >> 4;
    float acc[8][8];
    #pragma unroll
    for (int r=0;r<8;r++)
        #pragma unroll
        for (int c=0;c<8;c++) acc[r][c] = 0.f;
    if (t < 128) { s_sum[t] = 0.f; s_ss[t] = 0.f; }
    for (int kc = 0; kc < 64; kc += 32) {
        __syncthreads();
        #pragma unroll
        for (int i=0;i<16;i++) { int f=t+i*256; int k=f>>7, o=f&127; As[k][o] = w2[o*64 + kc + k]; }
        #pragma unroll
        for (int i=0;i<16;i++) { int f=t+i*256; int k=f>>7, n=f&127;
            Bs[k][n] = g_h1[(b*64 + kc + k)*2048 + n0 + n]; }
        __syncthreads();
        #pragma unroll
        for (int k=0;k<32;k++) {
            float a[8], bb[8];
            *(float4*)&a[0]  = *(const float4*)&As[k][ty*8];
            *(float4*)&a[4]  = *(const float4*)&As[k][ty*8+4];
            *(float4*)&bb[0] = *(const float4*)&Bs[k][tx*8];
            *(float4*)&bb[4] = *(const float4*)&Bs[k][tx*8+4];
            #pragma unroll
            for (int r=0;r<8;r++)
                #pragma unroll
                for (int c=0;c<8;c++) acc[r][c] = fmaf(a[r], bb[c], acc[r][c]);
        }
    }
    #pragma unroll
    for (int r=0;r<8;r++) {
        int o = ty*8 + r;
        float bias = b2[o];
        float rs = 0.f, rq = 0.f;
        float v[8];
        #pragma unroll
        for (int c=0;c<8;c++) { v[c] = acc[r][c] + bias; rs += v[c]; rq = fmaf(v[c], v[c], rq); }
        float* dst = &g_h2[(b*128+o)*2048 + n0 + tx*8];
        *(float4*)dst     = *(float4*)&v[0];
        *(float4*)(dst+4) = *(float4*)&v[4];
        atomicAdd(&s_sum[o], rs);
        atomicAdd(&s_ss[o], rq);
    }
    __syncthreads();
    if (t < 128) { atomicAdd(&g_c2sum[t], s_sum[t]); atomicAdd(&g_c2ss[t], s_ss[t]); }
}

// ---------------- BN2+relu (inline finalize) + transpose -> B fp16 hi ----------
__global__ void __launch_bounds__(256) k_split_b(const float* __restrict__ g2,
                                                 const float* __restrict__ be2) {
    __shared__ float smv[128][65];
    __shared__ float ssc[128], ssh[128];
    int b = blockIdx.y, n0 = blockIdx.x*64, t = threadIdx.x;
    if (t < 128) {
        float mean = g_c2sum[t] * (1.f/8192.f);
        float var = g_c2ss[t] * (1.f/8192.f) - mean*mean;
        float sc = g2[t]*rsqrtf(var + BEPS);
        ssc[t] = sc;
        ssh[t] = be2[t] - mean*sc;
    }
    __syncthreads();
    #pragma unroll
    for (int i=0;i<32;i++) {
        int f = t + i*256; int c = f >> 6, n = f & 63;
        float v = g_h2[(b*128+c)*2048 + n0 + n];
        smv[c][n] = fmaxf(fmaf(ssc[c], v, ssh[c]), 0.f);
    }
    __syncthreads();
    int col = t & 63, q = t >> 6;
    __half* dst = g_Bs + (size_t)(b*2048 + n0 + col)*128;
    #pragma unroll
    for (int ch=0; ch<32; ch++)
        dst[q*32+ch] = __float2half_rn(smv[q*32+ch][col]);
}

// ---------------- caps GEMM via WMMA fp16: D = A(hi+lo) · Bhi^T ----------------
// CTA tile 128(M) x 256(N), 8 warps (2Mx4N), warp tile 64x64 (4x4 frags).
// K = 256 (A chunks 0..7 = [hi|lo]); B chunk index = kc&3 (Bhi reused).
#define LDA 40
#define A_ST 10240                  // 128*40*2
#define B_ST 20480                  // 256*40*2
#define STG (A_ST + B_ST)           // 30720
#define CAPS_SMEM (3*STG)           // 92160
#define EP_LD 132

__global__ void __launch_bounds__(256) k_caps_wmma(const float* __restrict__ b3) {
    extern __shared__ char sm[];
    const uint32_t sb = smem_u32(sm);
    const int t = threadIdx.x, w = t >> 5;
    const int row0 = blockIdx.y * 128, col0 = blockIdx.x * 256;
    const int wm = (w >> 2) * 64, wn = (w & 3) * 64;

    wmma::fragment<wmma::accumulator,16,16,16,float> acc[4][4];
    #pragma unroll
    for (int r=0;r<4;r++)
        #pragma unroll
        for (int c=0;c<4;c++) wmma::fill_fragment(acc[r][c], 0.f);

    auto issue = [&](int stage, int kc) {
        uint32_t ab = sb + stage*STG;
        uint32_t bb = ab + A_ST;
        #pragma unroll
        for (int i=0;i<2;i++) {
            int idx = t + i*256; int r = idx >> 2, j = idx & 3;
            cp16(ab + (uint32_t)(r*LDA + j*8)*2,
                 g_As + (size_t)(row0 + r)*256 + kc*32 + j*8);
        }
        #pragma unroll
        for (int i=0;i<4;i++) {
            int idx = t + i*256; int r = idx >> 2, j = idx & 3;
            cp16(bb + (uint32_t)(r*LDA + j*8)*2,
                 g_Bs + (size_t)(col0 + r)*128 + (kc&3)*32 + j*8);
        }
        CP_COMMIT();
    };

    issue(0, 0);
    issue(1, 1);

    for (int kc = 0; kc < 8; kc++) {
        if (kc < 7) { CP_WAIT(1); } else { CP_WAIT(0); }
        __syncthreads();
        if (kc + 2 < 8) issue((kc+2)%3, kc+2);
        const __half* Asm = (const __half*)(sm + (kc%3)*STG);
        const __half* Bsm = (const __half*)(sm + (kc%3)*STG + A_ST);
        #pragma unroll
        for (int ks=0; ks<2; ks++) {
            wmma::fragment<wmma::matrix_a,16,16,16,__half,wmma::row_major> af[4];
            wmma::fragment<wmma::matrix_b,16,16,16,__half,wmma::col_major> bf[4];
            #pragma unroll
            for (int r=0;r<4;r++)
                wmma::load_matrix_sync(af[r], Asm + (wm + r*16)*LDA + ks*16, LDA);
            #pragma unroll
            for (int c=0;c<4;c++)
                wmma::load_matrix_sync(bf[c], Bsm + (wn + c*16)*LDA + ks*16, LDA);
            #pragma unroll
            for (int r=0;r<4;r++)
                #pragma unroll
                for (int c=0;c<4;c++)
                    wmma::mma_sync(acc[r][c], af[r], bf[c], acc[r][c]);
        }
    }
    __syncthreads();

    // epilogue: two half passes (N cols 0..127, 128..255)
    float* Ep = (float*)sm;
    int row = t >> 1, half = t & 1;
    float bias = b3[row0 + row];
    float s = 0.f, q = 0.f, mx = -3.4028235e38f, mn = 3.4028235e38f;
    #pragma unroll
    for (int h=0; h<2; h++) {
        __syncthreads();
        if ((wn >= 128 ? 1 : 0) == h) {
            #pragma unroll
            for (int r=0;r<4;r++)
                #pragma unroll
                for (int c=0;c<4;c++)
                    wmma::store_matrix_sync(Ep + (wm + r*16)*EP_LD + (wn & 127) + c*16,
                                            acc[r][c], EP_LD, wmma::mem_row_major);
        }
        __syncthreads();
        const float* pr = Ep + row*EP_LD + half*64;
        #pragma unroll
        for (int c=0;c<64;c++) {
            float v = pr[c] + bias;
            s += v; q = fmaf(v, v, q);
            mx = fmaxf(mx, v); mn = fminf(mn, v);
        }
    }
    s  += __shfl_xor_sync(0xffffffffu, s, 1);
    q  += __shfl_xor_sync(0xffffffffu, q, 1);
    mx = fmaxf(mx, __shfl_xor_sync(0xffffffffu, mx, 1));
    mn = fminf(mn, __shfl_xor_sync(0xffffffffu, mn, 1));
    if (half == 0) {
        int gi = (row0 + row)*32 + blockIdx.x;
        g_psum[gi] = s; g_pss[gi] = q; g_pmx[gi] = mx; g_pmn[gi] = mn;
    }
}

// ---------------- reduce partial stats -> rowstats ----------------
__global__ void k_redstats() {
    int row = blockIdx.x*256 + threadIdx.x;    // 16384 rows
    float s = 0.f, q = 0.f;
    float mx[4], mn[4];
    #pragma unroll
    for (int b=0;b<4;b++) { mx[b] = -3.4028235e38f; mn[b] = 3.4028235e38f; }
    #pragma unroll
    for (int nt=0; nt<32; nt++) {
        int gi = row*32 + nt, b = nt >> 3;
        s += g_psum[gi]; q += g_pss[gi];
        mx[b] = fmaxf(mx[b], g_pmx[gi]);
        mn[b] = fminf(mn[b], g_pmn[gi]);
    }
    float* o = g_rowstats + row*10;
    o[0] = s; o[1] = q;
    #pragma unroll
    for (int b=0;b<4;b++) { o[2+b] = mx[b]; o[6+b] = mn[b]; }
}

// ---------------- finalize BN + max + squash -> u[b][p][q] ----------------
__global__ void k_ufin(const float* __restrict__ g3, const float* __restrict__ be3) {
    int idx = blockIdx.x*256 + threadIdx.x;   // 4096 (b,p)
    int b = idx >> 10, p = idx & 1023;
    float vq[16]; float sn = 0.f;
    #pragma unroll
    for (int q=0;q<16;q++) {
        int row = q*1024 + p;
        const float* st = g_rowstats + row*10;
        float mean = st[0]*(1.f/8192.f);
        float var  = st[1]*(1.f/8192.f) - mean*mean;
        float sc = g3[row]*rsqrtf(var + BEPS);
        float m = (sc >= 0.f) ? st[2+b] : st[6+b];   // BN affine is monotone
        float v = fmaf(sc, m - mean, be3[row]);
        vq[q] = v; sn = fmaf(v,v,sn);
    }
    float coef = sn/((1.f+sn)*sqrtf(sn));
    #pragma unroll
    for (int q=0;q<16;q++) g_u[(b*1024+p)*16 + q] = coef*vq[q];
}

// ---------------- u_hat = einsum(lpvq,bpq->blpv) ----------------
__global__ void k_uhat(const float* __restrict__ Wr) {
    int bid = blockIdx.x;                 // 16384: l, group of 4 p
    int l = bid >> 8, p0 = (bid & 255)*4;
    int t = threadIdx.x, pi = t >> 6, v = t & 63;
    int p = p0 + pi;
    __shared__ float us[4][4][16];        // [pi][b][q]
    { int pp = t>>6, bb=(t>>4)&3, q=t&15;
      us[pp][bb][q] = g_u[(bb*1024 + p0+pp)*16 + q]; }
    __syncthreads();
    const float* wr = Wr + (((long)(l*1024+p))*64 + v)*16;
    float4 a0 = *(const float4*)wr,     a1 = *(const float4*)(wr+4);
    float4 a2 = *(const float4*)(wr+8), a3 = *(const float4*)(wr+12);
    #pragma unroll
    for (int b=0;b<4;b++) {
        const float* u = us[pi][b];
        float d = a0.x*u[0]+a0.y*u[1]+a0.z*u[2]+a0.w*u[3]
                + a1.x*u[4]+a1.y*u[5]+a1.z*u[6]+a1.w*u[7]
                + a2.x*u[8]+a2.y*u[9]+a2.z*u[10]+a2.w*u[11]
                + a3.x*u[12]+a3.y*u[13]+a3.z*u[14]+a3.w*u[15];
        g_uhat[(((long)(b*64+l))*1024+p)*64 + v] = d;
    }
}

// ---------------- routing: softmax over L ----------------
__global__ void k_softmax() {
    int idx = blockIdx.x*256 + threadIdx.x;  // 4096 (b,p)
    int b = idx >> 10, p = idx & 1023;
    const float* bp = g_bij + b*65536 + p;
    float e[64]; float mx = -3.4e38f;
    #pragma unroll
    for (int l=0;l<64;l++){ e[l] = bp[l*1024]; mx = fmaxf(mx, e[l]); }
    float s = 0.f;
    #pragma unroll
    for (int l=0;l<64;l++){ e[l] = __expf(e[l]-mx); s += e[l]; }
    float inv = 1.f/s;
    float* cp = g_cij + b*65536 + p;
    #pragma unroll
    for (int l=0;l<64;l++) cp[l*1024] = e[l]*inv;
}

// ---------------- routing: v_j = squash(sum_p c*u_hat) ----------------
__global__ void k_vj() {
    int bid = blockIdx.x;                 // 256 (b,l)
    int b = bid >> 6, l = bid & 63;
    int t = threadIdx.x, v = t & 63, pc = t >> 6;
    __shared__ float cs[1024];
    __shared__ float red[4][64];
    __shared__ float sq[64];
    __shared__ float s_coef;
    for (int i=t;i<1024;i+=256) cs[i] = g_cij[(b*64+l)*1024 + i];
    __syncthreads();
    const float* uh = g_uhat + ((long)(b*64+l))*65536;
    float acc = 0.f;
    #pragma unroll 8
    for (int p = pc*256; p < pc*256+256; p++)
        acc = fmaf(cs[p], uh[p*64 + v], acc);
    red[pc][v] = acc;
    __syncthreads();
    if (t < 64) {
        float vr = red[0][t]+red[1][t]+red[2][t]+red[3][t];
        red[0][t] = vr;
        sq[t] = vr*vr;
    }
    __syncthreads();
    if (t == 0) {
        float sn = 0.f;
        for (int i=0;i<64;i++) sn += sq[i];
        s_coef = sn/((1.f+sn)*sqrtf(sn));
    }
    __syncthreads();
    if (t < 64) g_vj[(b*64+l)*64 + t] = s_coef*red[0][t];
}

// ---------------- routing: b_ij += <v_j, u_hat> ----------------
__global__ void k_bupd() {
    int bid = blockIdx.x;
    int b = bid >> 6, l = bid & 63;
    int t = threadIdx.x, lane = t & 31, w = t >> 5;
    __shared__ float vs[64];
    if (t < 64) vs[t] = g_vj[(b*64+l)*64 + t];
    __syncthreads();
    float v0 = vs[lane], v1 = vs[lane+32];
    const float* uh = g_uhat + ((long)(b*64+l))*65536;
    float* bp = g_bij + (b*64+l)*1024;
    for (int p = w; p < 1024; p += 8) {
        float d = fmaf(v0, uh[p*64+lane], v1*uh[p*64+lane+32]);
        #pragma unroll
        for (int off=16;off>0;off>>=1) d += __shfl_down_sync(0xffffffffu, d, off);
        if (lane==0) bp[p] += d;
    }
}

// ---------------- head: logits + presence ----------------
__global__ void k_logits(const float* __restrict__ fcw, const float* __restrict__ fcb,
                         float* __restrict__ out) {
    int bid = blockIdx.x;                 // 160 = 4*40
    int b = bid/40, o = bid%40;
    int t = threadIdx.x;                  // 128
    const float* vj = g_vj + b*4096;
    const float* wr = fcw + o*4096;
    float acc = 0.f;
    for (int i=t;i<4096;i+=128) acc = fmaf(vj[i], wr[i], acc);
    __shared__ float red[4];
    #pragma unroll
    for (int off=16;off>0;off>>=1) acc += __shfl_down_sync(0xffffffffu, acc, off);
    if ((t&31)==0) red[t>>5]=acc;
    __syncthreads();
    if (t==0) out[b*40+o] = red[0]+red[1]+red[2]+red[3] + fcb[o];
}

__global__ void k_pres(float* __restrict__ out) {
    int t = threadIdx.x;                  // 256 = (b,l)
    const float* vj = g_vj + t*64;
    float s = 0.f;
    #pragma unroll
    for (int i=0;i<64;i++) s = fmaf(vj[i], vj[i], s);
    out[160 + t] = sqrtf(s);
}

// ---------------- launch ----------------
extern "C" void kernel_launch(void* const* d_in, const int* in_sizes, int n_in,
                              void* d_out, int out_size) {
    const float* x   = (const float*)d_in[0];
    const float* w1  = (const float*)d_in[1];
    const float* b1  = (const float*)d_in[2];
    const float* g1  = (const float*)d_in[3];
    const float* be1 = (const float*)d_in[4];
    const float* w2  = (const float*)d_in[5];
    const float* b2  = (const float*)d_in[6];
    const float* g2  = (const float*)d_in[7];
    const float* be2 = (const float*)d_in[8];
    const float* w3  = (const float*)d_in[9];
    const float* b3  = (const float*)d_in[10];
    const float* g3  = (const float*)d_in[11];
    const float* be3 = (const float*)d_in[12];
    const float* Wr  = (const float*)d_in[13];
    const float* fcw = (const float*)d_in[14];
    const float* fcb = (const float*)d_in[15];
    float* out = (float*)d_out;

    cudaFuncSetAttribute(k_caps_wmma, cudaFuncAttributeMaxDynamicSharedMemorySize, CAPS_SMEM);

    k_front<<<2433,256>>>(x,w1,b1,g1,be1,w3);        // launch 0
    k_conv2<<<dim3(16,4),256>>>(w2,b2);              // launch 1
    k_split_b<<<dim3(32,4),256>>>(g2,be2);           // launch 2
    k_caps_wmma<<<dim3(32,128),256,CAPS_SMEM>>>(b3); // launch 3  <- profiled
    k_redstats<<<64,256>>>();
    k_ufin<<<16,256>>>(g3,be3);
    k_uhat<<<16384,256>>>(Wr);
    for (int it=0; it<3; it++) {
        k_softmax<<<16,256>>>();
        k_vj<<<256,256>>>();
        if (it<2) k_bupd<<<256,256>>>();
    }
    k_logits<<<160,128>>>(fcw, fcb, out);
    k_pres<<<1,256>>>(out);
}

// round 7
// speedup vs baseline: 4.5465x; 1.2065x over previous
#include <cuda_runtime.h>
#include <cuda_fp16.h>
#include <mma.h>
#include <cstdint>
#include <math.h>

using namespace nvcuda;

#define BEPS 1e-5f

// ---------------- scratch (static device globals; no allocation) ----------------
__device__ float g_h1[4*64*2048];            // conv1 output (post BN+relu)
__device__ float g_h2[4*128*2048];           // conv2 pre-act
__device__ float g_c2sum[128], g_c2ss[128];
__device__ __align__(16) __half g_Ah[16384*128];  // A = fp16(w3)
__device__ __align__(16) __half g_Bs[8192*128];   // B = fp16(h2 post bn/relu), transposed
__device__ float g_psum[16384*32], g_pss[16384*32], g_pmx[16384*32], g_pmn[16384*32];
__device__ float g_rowstats[16384*10];       // per (q,p): sum, sumsq, max[4], min[4]
__device__ float g_u[4*1024*16];             // squashed primary caps [b][p][q]
__device__ float g_uhat[(long)4*64*1024*64]; // 67MB [b][l][p][v]
__device__ float g_bij[4*64*1024];
__device__ float g_cij[4*64*1024];
__device__ float g_vj[4*64*64];

__device__ __forceinline__ uint32_t smem_u32(const void* p) {
    uint32_t a;
    asm("{ .reg .u64 t; cvta.to.shared.u64 t, %1; cvt.u32.u64 %0, t; }" : "=r"(a) : "l"(p));
    return a;
}
__device__ __forceinline__ void cp16(uint32_t dst, const void* src) {
    asm volatile("cp.async.cg.shared.global [%0], [%1], 16;" :: "r"(dst), "l"(src));
}
#define CP_COMMIT() asm volatile("cp.async.commit_group;" ::: "memory")
#define CP_WAIT(n)  asm volatile("cp.async.wait_group %0;" :: "n"(n) : "memory")

// ---------------- front: conv1(+inline bn1) | cast w3 | zero bij/c2 ----------
__global__ void __launch_bounds__(256) k_front(const float* __restrict__ x,
        const float* __restrict__ w1, const float* __restrict__ b1,
        const float* __restrict__ g1, const float* __restrict__ be1,
        const float* __restrict__ w3) {
    int blk = blockIdx.x, t = threadIdx.x;
    if (blk < 128) {
        // ---- conv1 block with per-block analytic BN1 ----
        int nb = blk & 7, b = (blk >> 3) & 3, og = (blk >> 5) * 16;
        __shared__ float red[9][8];
        __shared__ float m[3], cov[3][3];
        __shared__ float ssc[16], ssh[16];
        float s0=0,s1=0,s2=0,p00=0,p01=0,p02=0,p11=0,p12=0,p22=0;
        for (int i = t; i < 8192; i += 256) {
            int bb = i >> 11, n = i & 2047;
            const float* xb = x + bb*3*2048 + n;
            float a = xb[0], c = xb[2048], d = xb[4096];
            s0+=a; s1+=c; s2+=d;
            p00+=a*a; p01+=a*c; p02+=a*d; p11+=c*c; p12+=c*d; p22+=d*d;
        }
        float vals[9] = {s0,s1,s2,p00,p01,p02,p11,p12,p22};
        int lane = t & 31, w = t >> 5;
        #pragma unroll
        for (int j=0;j<9;j++) {
            float v = vals[j];
            #pragma unroll
            for (int o=16;o>0;o>>=1) v += __shfl_down_sync(0xffffffffu, v, o);
            if (lane==0) red[j][w] = v;
        }
        __syncthreads();
        if (t < 9) {
            float v = 0;
            for (int ww=0; ww<8; ww++) v += red[t][ww];
            red[t][0] = v * (1.f/8192.f);
        }
        __syncthreads();
        if (t == 0) {
            m[0]=red[0][0]; m[1]=red[1][0]; m[2]=red[2][0];
            cov[0][0]=red[3][0]-m[0]*m[0];
            cov[0][1]=cov[1][0]=red[4][0]-m[0]*m[1];
            cov[0][2]=cov[2][0]=red[5][0]-m[0]*m[2];
            cov[1][1]=red[6][0]-m[1]*m[1];
            cov[1][2]=cov[2][1]=red[7][0]-m[1]*m[2];
            cov[2][2]=red[8][0]-m[2]*m[2];
        }
        __syncthreads();
        if (t < 16) {
            int o = og + t;
            float wv0=w1[o*3], wv1=w1[o*3+1], wv2=w1[o*3+2];
            float mean = wv0*m[0]+wv1*m[1]+wv2*m[2] + b1[o];
            float var = wv0*wv0*cov[0][0] + wv1*wv1*cov[1][1] + wv2*wv2*cov[2][2]
                      + 2.f*(wv0*wv1*cov[0][1] + wv0*wv2*cov[0][2] + wv1*wv2*cov[1][2]);
            float sc = g1[o]*rsqrtf(var + BEPS);
            ssc[t] = sc;
            ssh[t] = be1[o] - mean*sc;
        }
        __syncthreads();
        int n = nb*256 + t;
        float x0 = x[b*6144 + n], x1 = x[b*6144 + 2048 + n], x2 = x[b*6144 + 4096 + n];
        #pragma unroll
        for (int oo=0;oo<16;oo++) {
            int o = og + oo;
            float pre = fmaf(w1[o*3], x0, fmaf(w1[o*3+1], x1, fmaf(w1[o*3+2], x2, b1[o])));
            float h = fmaf(ssc[oo], pre, ssh[oo]);
            g_h1[(b*64+o)*2048 + n] = fmaxf(h, 0.f);
        }
    } else if (blk < 2176) {
        // ---- cast w3 -> fp16 ----
        int blk2 = blk - 128;
        #pragma unroll
        for (int i=0;i<4;i++) {
            int id = blk2*1024 + i*256 + t;
            g_Ah[id] = __float2half_rn(w3[id]);
        }
    } else if (blk < 2432) {
        int blk3 = blk - 2176;
        #pragma unroll
        for (int i=0;i<4;i++) g_bij[blk3*1024 + i*256 + t] = 0.f;
    } else {
        if (t < 128) { g_c2sum[t] = 0.f; g_c2ss[t] = 0.f; }
    }
}

// ---------------- conv2: tiled GEMM 128o x 128n, K=64, pre-act + stats ----------
__global__ void __launch_bounds__(256) k_conv2(const float* __restrict__ w2,
                                               const float* __restrict__ b2) {
    __shared__ float As[32][128];   // As[k][o]
    __shared__ float Bs[32][128];   // Bs[k][n]
    __shared__ float s_sum[128], s_ss[128];
    int b = blockIdx.y, n0 = blockIdx.x*128, t = threadIdx.x;
    int tx = t & 15, ty = t >> 4;
    float acc[8][8];
    #pragma unroll
    for (int r=0;r<8;r++)
        #pragma unroll
        for (int c=0;c<8;c++) acc[r][c] = 0.f;
    if (t < 128) { s_sum[t] = 0.f; s_ss[t] = 0.f; }
    for (int kc = 0; kc < 64; kc += 32) {
        __syncthreads();
        #pragma unroll
        for (int i=0;i<16;i++) { int f=t+i*256; int k=f>>7, o=f&127; As[k][o] = w2[o*64 + kc + k]; }
        #pragma unroll
        for (int i=0;i<16;i++) { int f=t+i*256; int k=f>>7, n=f&127;
            Bs[k][n] = g_h1[(b*64 + kc + k)*2048 + n0 + n]; }
        __syncthreads();
        #pragma unroll
        for (int k=0;k<32;k++) {
            float a[8], bb[8];
            *(float4*)&a[0]  = *(const float4*)&As[k][ty*8];
            *(float4*)&a[4]  = *(const float4*)&As[k][ty*8+4];
            *(float4*)&bb[0] = *(const float4*)&Bs[k][tx*8];
            *(float4*)&bb[4] = *(const float4*)&Bs[k][tx*8+4];
            #pragma unroll
            for (int r=0;r<8;r++)
                #pragma unroll
                for (int c=0;c<8;c++) acc[r][c] = fmaf(a[r], bb[c], acc[r][c]);
        }
    }
    #pragma unroll
    for (int r=0;r<8;r++) {
        int o = ty*8 + r;
        float bias = b2[o];
        float rs = 0.f, rq = 0.f;
        float v[8];
        #pragma unroll
        for (int c=0;c<8;c++) { v[c] = acc[r][c] + bias; rs += v[c]; rq = fmaf(v[c], v[c], rq); }
        float* dst = &g_h2[(b*128+o)*2048 + n0 + tx*8];
        *(float4*)dst     = *(float4*)&v[0];
        *(float4*)(dst+4) = *(float4*)&v[4];
        atomicAdd(&s_sum[o], rs);
        atomicAdd(&s_ss[o], rq);
    }
    __syncthreads();
    if (t < 128) { atomicAdd(&g_c2sum[t], s_sum[t]); atomicAdd(&g_c2ss[t], s_ss[t]); }
}

// ---------------- BN2+relu (inline finalize) + transpose -> B fp16 ----------
__global__ void __launch_bounds__(256) k_split_b(const float* __restrict__ g2,
                                                 const float* __restrict__ be2) {
    __shared__ float smv[128][65];
    __shared__ float ssc[128], ssh[128];
    int b = blockIdx.y, n0 = blockIdx.x*64, t = threadIdx.x;
    if (t < 128) {
        float mean = g_c2sum[t] * (1.f/8192.f);
        float var = g_c2ss[t] * (1.f/8192.f) - mean*mean;
        float sc = g2[t]*rsqrtf(var + BEPS);
        ssc[t] = sc;
        ssh[t] = be2[t] - mean*sc;
    }
    __syncthreads();
    #pragma unroll
    for (int i=0;i<32;i++) {
        int f = t + i*256; int c = f >> 6, n = f & 63;
        float v = g_h2[(b*128+c)*2048 + n0 + n];
        smv[c][n] = fmaxf(fmaf(ssc[c], v, ssh[c]), 0.f);
    }
    __syncthreads();
    int col = t & 63, q = t >> 6;
    __half* dst = g_Bs + (size_t)(b*2048 + n0 + col)*128;
    #pragma unroll
    for (int ch=0; ch<32; ch++)
        dst[q*32+ch] = __float2half_rn(smv[q*32+ch][col]);
}

// ---------------- caps GEMM via WMMA fp16: D = A · B^T, K=128 ----------------
// CTA tile 128(M) x 256(N), 8 warps (2Mx4N), warp tile 64x64 (4x4 frags).
// K = 128, chunks of 32 (4 chunks), 3-stage cp.async pipeline.
#define LDA 40
#define A_ST 10240                  // 128*40*2
#define B_ST 20480                  // 256*40*2
#define STG (A_ST + B_ST)           // 30720
#define CAPS_SMEM (3*STG)           // 92160
#define EP_LD 132

__global__ void __launch_bounds__(256) k_caps_wmma(const float* __restrict__ b3) {
    extern __shared__ char sm[];
    const uint32_t sb = smem_u32(sm);
    const int t = threadIdx.x, w = t >> 5;
    const int row0 = blockIdx.y * 128, col0 = blockIdx.x * 256;
    const int wm = (w >> 2) * 64, wn = (w & 3) * 64;

    wmma::fragment<wmma::accumulator,16,16,16,float> acc[4][4];
    #pragma unroll
    for (int r=0;r<4;r++)
        #pragma unroll
        for (int c=0;c<4;c++) wmma::fill_fragment(acc[r][c], 0.f);

    auto issue = [&](int stage, int kc) {
        uint32_t ab = sb + stage*STG;
        uint32_t bb = ab + A_ST;
        #pragma unroll
        for (int i=0;i<2;i++) {
            int idx = t + i*256; int r = idx >> 2, j = idx & 3;
            cp16(ab + (uint32_t)(r*LDA + j*8)*2,
                 g_Ah + (size_t)(row0 + r)*128 + kc*32 + j*8);
        }
        #pragma unroll
        for (int i=0;i<4;i++) {
            int idx = t + i*256; int r = idx >> 2, j = idx & 3;
            cp16(bb + (uint32_t)(r*LDA + j*8)*2,
                 g_Bs + (size_t)(col0 + r)*128 + kc*32 + j*8);
        }
        CP_COMMIT();
    };

    issue(0, 0);
    issue(1, 1);

    for (int kc = 0; kc < 4; kc++) {
        if (kc < 3) { CP_WAIT(1); } else { CP_WAIT(0); }
        __syncthreads();
        if (kc + 2 < 4) issue((kc+2)%3, kc+2);
        const __half* Asm = (const __half*)(sm + (kc%3)*STG);
        const __half* Bsm = (const __half*)(sm + (kc%3)*STG + A_ST);
        #pragma unroll
        for (int ks=0; ks<2; ks++) {
            wmma::fragment<wmma::matrix_a,16,16,16,__half,wmma::row_major> af[4];
            wmma::fragment<wmma::matrix_b,16,16,16,__half,wmma::col_major> bf[4];
            #pragma unroll
            for (int r=0;r<4;r++)
                wmma::load_matrix_sync(af[r], Asm + (wm + r*16)*LDA + ks*16, LDA);
            #pragma unroll
            for (int c=0;c<4;c++)
                wmma::load_matrix_sync(bf[c], Bsm + (wn + c*16)*LDA + ks*16, LDA);
            #pragma unroll
            for (int r=0;r<4;r++)
                #pragma unroll
                for (int c=0;c<4;c++)
                    wmma::mma_sync(acc[r][c], af[r], bf[c], acc[r][c]);
        }
    }
    __syncthreads();

    // epilogue: two half passes (N cols 0..127, 128..255)
    float* Ep = (float*)sm;
    int row = t >> 1, half = t & 1;
    float bias = b3[row0 + row];
    float s = 0.f, q = 0.f, mx = -3.4028235e38f, mn = 3.4028235e38f;
    #pragma unroll
    for (int h=0; h<2; h++) {
        __syncthreads();
        if ((wn >= 128 ? 1 : 0) == h) {
            #pragma unroll
            for (int r=0;r<4;r++)
                #pragma unroll
                for (int c=0;c<4;c++)
                    wmma::store_matrix_sync(Ep + (wm + r*16)*EP_LD + (wn & 127) + c*16,
                                            acc[r][c], EP_LD, wmma::mem_row_major);
        }
        __syncthreads();
        const float* pr = Ep + row*EP_LD + half*64;
        #pragma unroll
        for (int c=0;c<64;c++) {
            float v = pr[c] + bias;
            s += v; q = fmaf(v, v, q);
            mx = fmaxf(mx, v); mn = fminf(mn, v);
        }
    }
    s  += __shfl_xor_sync(0xffffffffu, s, 1);
    q  += __shfl_xor_sync(0xffffffffu, q, 1);
    mx = fmaxf(mx, __shfl_xor_sync(0xffffffffu, mx, 1));
    mn = fminf(mn, __shfl_xor_sync(0xffffffffu, mn, 1));
    if (half == 0) {
        int gi = (row0 + row)*32 + blockIdx.x;
        g_psum[gi] = s; g_pss[gi] = q; g_pmx[gi] = mx; g_pmn[gi] = mn;
    }
}

// ---------------- reduce partial stats -> rowstats ----------------
__global__ void k_redstats() {
    int row = blockIdx.x*256 + threadIdx.x;    // 16384 rows
    float s = 0.f, q = 0.f;
    float mx[4], mn[4];
    #pragma unroll
    for (int b=0;b<4;b++) { mx[b] = -3.4028235e38f; mn[b] = 3.4028235e38f; }
    #pragma unroll
    for (int nt=0; nt<32; nt++) {
        int gi = row*32 + nt, b = nt >> 3;
        s += g_psum[gi]; q += g_pss[gi];
        mx[b] = fmaxf(mx[b], g_pmx[gi]);
        mn[b] = fminf(mn[b], g_pmn[gi]);
    }
    float* o = g_rowstats + row*10;
    o[0] = s; o[1] = q;
    #pragma unroll
    for (int b=0;b<4;b++) { o[2+b] = mx[b]; o[6+b] = mn[b]; }
}

// ---------------- finalize BN + max + squash -> u[b][p][q] ----------------
__global__ void k_ufin(const float* __restrict__ g3, const float* __restrict__ be3) {
    int idx = blockIdx.x*256 + threadIdx.x;   // 4096 (b,p)
    int b = idx >> 10, p = idx & 1023;
    float vq[16]; float sn = 0.f;
    #pragma unroll
    for (int q=0;q<16;q++) {
        int row = q*1024 + p;
        const float* st = g_rowstats + row*10;
        float mean = st[0]*(1.f/8192.f);
        float var  = st[1]*(1.f/8192.f) - mean*mean;
        float sc = g3[row]*rsqrtf(var + BEPS);
        float m = (sc >= 0.f) ? st[2+b] : st[6+b];   // BN affine is monotone
        float v = fmaf(sc, m - mean, be3[row]);
        vq[q] = v; sn = fmaf(v,v,sn);
    }
    float coef = sn/((1.f+sn)*sqrtf(sn));
    #pragma unroll
    for (int q=0;q<16;q++) g_u[(b*1024+p)*16 + q] = coef*vq[q];
}

// ---------------- u_hat = einsum(lpvq,bpq->blpv) ----------------
__global__ void k_uhat(const float* __restrict__ Wr) {
    int bid = blockIdx.x;                 // 16384: l, group of 4 p
    int l = bid >> 8, p0 = (bid & 255)*4;
    int t = threadIdx.x, pi = t >> 6, v = t & 63;
    int p = p0 + pi;
    __shared__ float us[4][4][16];        // [pi][b][q]
    { int pp = t>>6, bb=(t>>4)&3, q=t&15;
      us[pp][bb][q] = g_u[(bb*1024 + p0+pp)*16 + q]; }
    __syncthreads();
    const float* wr = Wr + (((long)(l*1024+p))*64 + v)*16;
    float4 a0 = *(const float4*)wr,     a1 = *(const float4*)(wr+4);
    float4 a2 = *(const float4*)(wr+8), a3 = *(const float4*)(wr+12);
    #pragma unroll
    for (int b=0;b<4;b++) {
        const float* u = us[pi][b];
        float d = a0.x*u[0]+a0.y*u[1]+a0.z*u[2]+a0.w*u[3]
                + a1.x*u[4]+a1.y*u[5]+a1.z*u[6]+a1.w*u[7]
                + a2.x*u[8]+a2.y*u[9]+a2.z*u[10]+a2.w*u[11]
                + a3.x*u[12]+a3.y*u[13]+a3.z*u[14]+a3.w*u[15];
        g_uhat[(((long)(b*64+l))*1024+p)*64 + v] = d;
    }
}

// ---------------- routing: softmax over L ----------------
__global__ void k_softmax() {
    int idx = blockIdx.x*256 + threadIdx.x;  // 4096 (b,p)
    int b = idx >> 10, p = idx & 1023;
    const float* bp = g_bij + b*65536 + p;
    float e[64]; float mx = -3.4e38f;
    #pragma unroll
    for (int l=0;l<64;l++){ e[l] = bp[l*1024]; mx = fmaxf(mx, e[l]); }
    float s = 0.f;
    #pragma unroll
    for (int l=0;l<64;l++){ e[l] = __expf(e[l]-mx); s += e[l]; }
    float inv = 1.f/s;
    float* cp = g_cij + b*65536 + p;
    #pragma unroll
    for (int l=0;l<64;l++) cp[l*1024] = e[l]*inv;
}

// ---------------- routing: v_j = squash(sum_p c*u_hat) ----------------
__global__ void k_vj() {
    int bid = blockIdx.x;                 // 256 (b,l)
    int b = bid >> 6, l = bid & 63;
    int t = threadIdx.x, v = t & 63, pc = t >> 6;
    __shared__ float cs[1024];
    __shared__ float red[4][64];
    __shared__ float sq[64];
    __shared__ float s_coef;
    for (int i=t;i<1024;i+=256) cs[i] = g_cij[(b*64+l)*1024 + i];
    __syncthreads();
    const float* uh = g_uhat + ((long)(b*64+l))*65536;
    float acc = 0.f;
    #pragma unroll 8
    for (int p = pc*256; p < pc*256+256; p++)
        acc = fmaf(cs[p], uh[p*64 + v], acc);
    red[pc][v] = acc;
    __syncthreads();
    if (t < 64) {
        float vr = red[0][t]+red[1][t]+red[2][t]+red[3][t];
        red[0][t] = vr;
        sq[t] = vr*vr;
    }
    __syncthreads();
    if (t == 0) {
        float sn = 0.f;
        for (int i=0;i<64;i++) sn += sq[i];
        s_coef = sn/((1.f+sn)*sqrtf(sn));
    }
    __syncthreads();
    if (t < 64) g_vj[(b*64+l)*64 + t] = s_coef*red[0][t];
}

// ---------------- routing: b_ij += <v_j, u_hat> ----------------
__global__ void k_bupd() {
    int bid = blockIdx.x;
    int b = bid >> 6, l = bid & 63;
    int t = threadIdx.x, lane = t & 31, w = t >> 5;
    __shared__ float vs[64];
    if (t < 64) vs[t] = g_vj[(b*64+l)*64 + t];
    __syncthreads();
    float v0 = vs[lane], v1 = vs[lane+32];
    const float* uh = g_uhat + ((long)(b*64+l))*65536;
    float* bp = g_bij + (b*64+l)*1024;
    for (int p = w; p < 1024; p += 8) {
        float d = fmaf(v0, uh[p*64+lane], v1*uh[p*64+lane+32]);
        #pragma unroll
        for (int off=16;off>0;off>>=1) d += __shfl_down_sync(0xffffffffu, d, off);
        if (lane==0) bp[p] += d;
    }
}

// ---------------- head: logits + presence ----------------
__global__ void k_logits(const float* __restrict__ fcw, const float* __restrict__ fcb,
                         float* __restrict__ out) {
    int bid = blockIdx.x;                 // 160 = 4*40
    int b = bid/40, o = bid%40;
    int t = threadIdx.x;                  // 128
    const float* vj = g_vj + b*4096;
    const float* wr = fcw + o*4096;
    float acc = 0.f;
    for (int i=t;i<4096;i+=128) acc = fmaf(vj[i], wr[i], acc);
    __shared__ float red[4];
    #pragma unroll
    for (int off=16;off>0;off>>=1) acc += __shfl_down_sync(0xffffffffu, acc, off);
    if ((t&31)==0) red[t>>5]=acc;
    __syncthreads();
    if (t==0) out[b*40+o] = red[0]+red[1]+red[2]+red[3] + fcb[o];
}

__global__ void k_pres(float* __restrict__ out) {
    int t = threadIdx.x;                  // 256 = (b,l)
    const float* vj = g_vj + t*64;
    float s = 0.f;
    #pragma unroll
    for (int i=0;i<64;i++) s = fmaf(vj[i], vj[i], s);
    out[160 + t] = sqrtf(s);
}

// ---------------- launch ----------------
extern "C" void kernel_launch(void* const* d_in, const int* in_sizes, int n_in,
                              void* d_out, int out_size) {
    const float* x   = (const float*)d_in[0];
    const float* w1  = (const float*)d_in[1];
    const float* b1  = (const float*)d_in[2];
    const float* g1  = (const float*)d_in[3];
    const float* be1 = (const float*)d_in[4];
    const float* w2  = (const float*)d_in[5];
    const float* b2  = (const float*)d_in[6];
    const float* g2  = (const float*)d_in[7];
    const float* be2 = (const float*)d_in[8];
    const float* w3  = (const float*)d_in[9];
    const float* b3  = (const float*)d_in[10];
    const float* g3  = (const float*)d_in[11];
    const float* be3 = (const float*)d_in[12];
    const float* Wr  = (const float*)d_in[13];
    const float* fcw = (const float*)d_in[14];
    const float* fcb = (const float*)d_in[15];
    float* out = (float*)d_out;

    cudaFuncSetAttribute(k_caps_wmma, cudaFuncAttributeMaxDynamicSharedMemorySize, CAPS_SMEM);

    k_front<<<2433,256>>>(x,w1,b1,g1,be1,w3);        // launch 0
    k_conv2<<<dim3(16,4),256>>>(w2,b2);              // launch 1
    k_split_b<<<dim3(32,4),256>>>(g2,be2);           // launch 2
    k_caps_wmma<<<dim3(32,128),256,CAPS_SMEM>>>(b3); // launch 3  <- profiled
    k_redstats<<<64,256>>>();
    k_ufin<<<16,256>>>(g3,be3);
    k_uhat<<<16384,256>>>(Wr);
    for (int it=0; it<3; it++) {
        k_softmax<<<16,256>>>();
        k_vj<<<256,256>>>();
        if (it<2) k_bupd<<<256,256>>>();
    }
    k_logits<<<160,128>>>(fcw, fcb, out);
    k_pres<<<1,256>>>(out);
}